// round 9
// baseline (speedup 1.0000x reference)
#include <cuda_runtime.h>
#include <cuda_bf16.h>
#include <math.h>
#include <stdint.h>

// Problem constants
#define BATCH 4
#define SLEN  2048
#define EMB   1024
#define QKVF  3072

// Quantization scales (static, distribution-derived; clamped/saturating)
#define SXQ   (6.0f/127.0f)     // X, q, k, V scale
#define SWQ   (0.2f/127.0f)     // W_qkv scale

// ---------------------------------------------------------------------------
// Device scratch
// ---------------------------------------------------------------------------
__device__ __align__(256) int8_t g_X8h[(size_t)BATCH*SLEN*EMB];
__device__ __align__(256) int8_t g_X8l[(size_t)BATCH*SLEN*EMB];
__device__ __align__(256) int8_t g_Wq8h[(size_t)QKVF*EMB];
__device__ __align__(256) int8_t g_Wq8l[(size_t)QKVF*EMB];
__device__ __align__(256) __nv_bfloat16 g_Woh[(size_t)EMB*EMB];
__device__ __align__(256) __nv_bfloat16 g_Wol[(size_t)EMB*EMB];
__device__ __align__(256) int8_t g_q8h[(size_t)BATCH*SLEN*EMB];
__device__ __align__(256) int8_t g_q8l[(size_t)BATCH*SLEN*EMB];
__device__ __align__(256) int8_t g_k8h[(size_t)BATCH*SLEN*EMB];
__device__ __align__(256) int8_t g_k8l[(size_t)BATCH*SLEN*EMB];
__device__ __align__(256) int8_t g_v8th[(size_t)BATCH*EMB*SLEN];  // V^T [b,e,s]
__device__ __align__(256) int8_t g_v8tl[(size_t)BATCH*EMB*SLEN];
__device__ __align__(256) float  g_att[(size_t)BATCH*SLEN*SLEN];
__device__ __align__(256) int8_t g_at8h[(size_t)BATCH*SLEN*SLEN];
__device__ __align__(256) int8_t g_at8l[(size_t)BATCH*SLEN*SLEN];
__device__ __align__(256) float  g_rs[(size_t)BATCH*SLEN];        // att row scales
__device__ __align__(256) __nv_bfloat16 g_ch[(size_t)BATCH*SLEN*EMB];
__device__ __align__(256) __nv_bfloat16 g_cl[(size_t)BATCH*SLEN*EMB];

// ---------------------------------------------------------------------------
// PTX helpers (sm_80+ only)
// ---------------------------------------------------------------------------
__device__ __forceinline__ uint32_t smem_u32(const void* p) {
    uint32_t a;
    asm("{ .reg .u64 t; cvta.to.shared.u64 t, %1; cvt.u32.u64 %0, t; }"
        : "=r"(a) : "l"(p));
    return a;
}
#define CP16(d, s)   asm volatile("cp.async.cg.shared.global [%0], [%1], 16;" :: "r"(d), "l"(s))
#define CP_COMMIT()  asm volatile("cp.async.commit_group;" ::: "memory")
#define CP_WAIT0()   asm volatile("cp.async.wait_group 0;" ::: "memory")

__device__ __forceinline__ void ldsm4(uint32_t* r, uint32_t addr) {
    asm volatile("ldmatrix.sync.aligned.m8n8.x4.shared.b16 {%0,%1,%2,%3}, [%4];"
        : "=r"(r[0]), "=r"(r[1]), "=r"(r[2]), "=r"(r[3]) : "r"(addr));
}
__device__ __forceinline__ void mma16816(float* d, const uint32_t* a, const uint32_t* b) {
    asm volatile("mma.sync.aligned.m16n8k16.row.col.f32.bf16.bf16.f32 "
        "{%0,%1,%2,%3}, {%4,%5,%6,%7}, {%8,%9}, {%0,%1,%2,%3};"
        : "+f"(d[0]), "+f"(d[1]), "+f"(d[2]), "+f"(d[3])
        : "r"(a[0]), "r"(a[1]), "r"(a[2]), "r"(a[3]), "r"(b[0]), "r"(b[1]));
}
__device__ __forceinline__ void imma16832(int* d, const uint32_t* a, const uint32_t* b) {
    asm volatile("mma.sync.aligned.m16n8k32.row.col.s32.s8.s8.s32 "
        "{%0,%1,%2,%3}, {%4,%5,%6,%7}, {%8,%9}, {%0,%1,%2,%3};"
        : "+r"(d[0]), "+r"(d[1]), "+r"(d[2]), "+r"(d[3])
        : "r"(a[0]), "r"(a[1]), "r"(a[2]), "r"(a[3]), "r"(b[0]), "r"(b[1]));
}

// int8 2-limb quantization: x ~= s*(h + l/128)
__device__ __forceinline__ void q8pair(float x, float s, float invs,
                                       int8_t& h, int8_t& l) {
    float hf = rintf(x * invs);
    hf = fminf(fmaxf(hf, -127.f), 127.f);
    float lf = rintf((x - hf * s) * invs * 128.f);
    lf = fminf(fmaxf(lf, -127.f), 127.f);
    h = (int8_t)hf;
    l = (int8_t)lf;
}

// ---- int8 GEMM tiling: CTA 128x128, BK=128 (4 x k32), 8 warps (2x4) ----
#define ROWB8   144                 // 128 s8 = 128B padded to 144B
#define TILE8   (128 * ROWB8)       // 18432 B
#define STAGE8  (4 * TILE8)         // Ah,Al,Bh,Bl = 73728 B
#define IG_SMEM (2 * STAGE8 + 128)  // 147584 B -> 1 CTA/SM

// ---- bf16 GEMM tiling (out-proj only): CTA 128x128, BK=32 ----
#define ROWB16   80
#define TILE16   (128 * ROWB16)
#define STAGE16  (4 * TILE16)
#define G16_SMEM (2 * STAGE16 + 128)

// ---------------------------------------------------------------------------
// int8 2-limb GEMM NT:  D = s1 * (acc_hh + acc_cross/128)
// MODE 0: qkv  (A=X8,B=W8; +bias; emit q/k int8 limbs, V^T int8 limbs)
// MODE 1: scores (A=q8,B=k8; fp32 att out, batched)
// MODE 2: ctx  (A=att8 row-scaled, B=V^T8; emit ctx bf16 hi/lo)
// ---------------------------------------------------------------------------
template<int MODE>
__global__ void __launch_bounds__(256, 1)
igemm_k(const int8_t* __restrict__ Ah, const int8_t* __restrict__ Al,
        size_t sA, int ldA,
        const int8_t* __restrict__ Bh, const int8_t* __restrict__ Bl,
        size_t sB, int ldB, int K, float s1,
        float* __restrict__ outF, size_t sF, int ldF,
        int8_t* __restrict__ qh8, int8_t* __restrict__ ql8,
        int8_t* __restrict__ kh8, int8_t* __restrict__ kl8,
        int8_t* __restrict__ vth8, int8_t* __restrict__ vtl8,
        __nv_bfloat16* __restrict__ ch, __nv_bfloat16* __restrict__ cl,
        const float* __restrict__ rowscale,
        const float* __restrict__ bias)
{
    extern __shared__ char dsm[];
    const uint32_t sb0 = smem_u32(dsm);
    const uint32_t SB  = (sb0 + 127u) & ~127u;
    float* stg = (float*)(dsm + (SB - sb0));    // epilogue staging [128][132]

    const int tid  = threadIdx.x;
    const int wid  = tid >> 5, lane = tid & 31;
    const int wm   = wid >> 2, wn = wid & 3;    // warp grid 2x4, warp tile 64x32
    const int bx = blockIdx.x, by = blockIdx.y, z = blockIdx.z;

    const int8_t* baseA_h = Ah + (size_t)z * sA + (size_t)by * 128 * ldA;
    const int8_t* baseA_l = Al + (size_t)z * sA + (size_t)by * 128 * ldA;
    const int8_t* baseB_h = Bh + (size_t)z * sB + (size_t)bx * 128 * ldB;
    const int8_t* baseB_l = Bl + (size_t)z * sB + (size_t)bx * 128 * ldB;

    auto load_chunk = [&](int c, int s) {
        const uint32_t stb = SB + (uint32_t)s * STAGE8;
        #pragma unroll
        for (int i = 0; i < 16; i++) {
            const int id = i * 256 + tid;       // 0..4095
            const int tt = id >> 10;            // operand tile 0..3
            const int u  = id & 1023;
            const int r  = u >> 3;              // row 0..127
            const int c16 = u & 7;              // 16B piece 0..7
            const int8_t* base = (tt == 0) ? baseA_h : (tt == 1) ? baseA_l
                               : (tt == 2) ? baseB_h : baseB_l;
            const int ld = (tt < 2) ? ldA : ldB;
            const int8_t* src = base + (size_t)r * ld + (size_t)c * 128 + (size_t)c16 * 16;
            const uint32_t dst = stb + (uint32_t)tt * TILE8 + (uint32_t)(r * ROWB8 + c16 * 16);
            CP16(dst, src);
        }
        CP_COMMIT();
    };

    int acc1[4][4][4], acc2[4][4][4];
    #pragma unroll
    for (int a = 0; a < 4; a++)
        #pragma unroll
        for (int b = 0; b < 4; b++)
            #pragma unroll
            for (int e = 0; e < 4; e++) { acc1[a][b][e] = 0; acc2[a][b][e] = 0; }

    const int NC = K >> 7;          // BK=128
    load_chunk(0, 0);

    const uint32_t offA = (uint32_t)((wm * 64 + (lane & 7) + ((lane >> 3) & 1) * 8) * ROWB8
                                     + ((lane >> 4) & 1) * 16);
    const uint32_t offB = (uint32_t)((wn * 32 + ((lane >> 4) & 1) * 8 + (lane & 7)) * ROWB8
                                     + ((lane >> 3) & 1) * 16);

    for (int c = 0; c < NC; c++) {
        CP_WAIT0();
        __syncthreads();
        const int s = c & 1;
        if (c + 1 < NC) load_chunk(c + 1, s ^ 1);

        const uint32_t stb = SB + (uint32_t)s * STAGE8;
        const uint32_t Ah_s = stb,            Al_s = stb + TILE8;
        const uint32_t Bh_s = stb + 2*TILE8,  Bl_s = stb + 3*TILE8;

        #pragma unroll
        for (int kk = 0; kk < 4; kk++) {        // 4 x k32 per chunk
            uint32_t bh[8], bl[8];
            ldsm4(&bh[0], Bh_s + offB + (uint32_t)(kk * 32));
            ldsm4(&bh[4], Bh_s + offB + (uint32_t)(16 * ROWB8 + kk * 32));
            ldsm4(&bl[0], Bl_s + offB + (uint32_t)(kk * 32));
            ldsm4(&bl[4], Bl_s + offB + (uint32_t)(16 * ROWB8 + kk * 32));
            #pragma unroll
            for (int mt = 0; mt < 4; mt++) {
                uint32_t ah[4], al[4];
                const uint32_t o = (uint32_t)(mt * 16 * ROWB8) + (uint32_t)(kk * 32);
                ldsm4(ah, Ah_s + offA + o);
                ldsm4(al, Al_s + offA + o);
                #pragma unroll
                for (int nt = 0; nt < 4; nt++) {
                    imma16832(acc1[mt][nt], ah, &bh[nt * 2]);   // hi*hi
                    imma16832(acc2[mt][nt], ah, &bl[nt * 2]);   // hi*lo
                    imma16832(acc2[mt][nt], al, &bh[nt * 2]);   // lo*hi
                }
            }
        }
    }
    __syncthreads();

    // ---- accumulators -> smem staging (scale + bias) ----
    #pragma unroll
    for (int mt = 0; mt < 4; mt++) {
        #pragma unroll
        for (int nt = 0; nt < 4; nt++) {
            const int r0 = wm * 64 + mt * 16 + (lane >> 2);
            const int c0 = wn * 32 + nt * 8 + (lane & 3) * 2;
            #pragma unroll
            for (int h = 0; h < 2; h++) {
                const int row = r0 + h * 8;
                float sc = s1;
                if (MODE == 2)
                    sc = rowscale[(size_t)z * SLEN + by * 128 + row] * s1;
                float v0 = ((float)acc1[mt][nt][h*2+0]
                          + (float)acc2[mt][nt][h*2+0] * 0.0078125f) * sc;
                float v1 = ((float)acc1[mt][nt][h*2+1]
                          + (float)acc2[mt][nt][h*2+1] * 0.0078125f) * sc;
                if (MODE == 0) {
                    v0 += bias[bx * 128 + c0];
                    v1 += bias[bx * 128 + c0 + 1];
                }
                *(float2*)&stg[row * 132 + c0] = make_float2(v0, v1);
            }
        }
    }
    __syncthreads();

    // ---- MODE-specific writers ----
    if (MODE == 1) {
        const int row = tid >> 1, h = tid & 1;
        float* dst = outF + (size_t)z * sF + ((size_t)by * 128 + row) * ldF
                   + (size_t)bx * 128 + h * 64;
        #pragma unroll
        for (int q = 0; q < 16; q++) {
            float4 v;
            v.x = stg[row * 132 + h * 64 + q * 4 + 0];
            v.y = stg[row * 132 + h * 64 + q * 4 + 1];
            v.z = stg[row * 132 + h * 64 + q * 4 + 2];
            v.w = stg[row * 132 + h * 64 + q * 4 + 3];
            ((float4*)dst)[q] = v;
        }
    } else if (MODE == 2) {
        // ctx -> bf16 hi/lo (row-major)
        #pragma unroll 1
        for (int cb = 0; cb < 4; cb++) {
            #pragma unroll 1
            for (int it = 0; it < 2; it++) {
                const int row = it * 64 + (tid >> 2);
                const int qq  = tid & 3;
                const int col = cb * 32 + qq * 8;
                const size_t rg = (size_t)z * SLEN + (size_t)by * 128 + row;
                const int colE = bx * 128 + col;
                union { __nv_bfloat16 b[8]; uint4 v; } Uh, Ul;
                #pragma unroll
                for (int i = 0; i < 8; i++) {
                    float v = stg[row * 132 + col + i];
                    __nv_bfloat16 hi = __float2bfloat16(v);
                    Uh.b[i] = hi;
                    Ul.b[i] = __float2bfloat16(v - __bfloat162float(hi));
                }
                const size_t off = rg * 1024 + colE;
                *(uint4*)(ch + off) = Uh.v;
                *(uint4*)(cl + off) = Ul.v;
            }
        }
    } else if (MODE == 0 && bx < 16) {
        // q/k -> int8 limbs (row-major)
        int8_t *OH, *OL;
        if (bx < 8) { OH = qh8; OL = ql8; } else { OH = kh8; OL = kl8; }
        const float invs = 127.0f / 6.0f, ss = SXQ;
        #pragma unroll 1
        for (int cb = 0; cb < 4; cb++) {
            #pragma unroll 1
            for (int it = 0; it < 2; it++) {
                const int row = it * 64 + (tid >> 2);
                const int qq  = tid & 3;
                const int col = cb * 32 + qq * 8;
                const size_t rg = (size_t)by * 128 + row;   // z==0 for qkv
                const int colE = (bx & 7) * 128 + col;
                union { int8_t b[8]; uint2 v; } Uh, Ul;
                #pragma unroll
                for (int i = 0; i < 8; i++)
                    q8pair(stg[row * 132 + col + i], ss, invs, Uh.b[i], Ul.b[i]);
                const size_t off = rg * 1024 + colE;
                *(uint2*)(OH + off) = Uh.v;
                *(uint2*)(OL + off) = Ul.v;
            }
        }
    } else if (MODE == 0) {
        // V tiles (bx 16..23): transposed int8 limbs to vt[b][e][s]
        const int j  = tid >> 3;       // 0..31
        const int rs = tid & 7;        // 16-row segment
        const int bidx = by >> 4;
        const int s0 = (by * 128) & 2047;
        const float invs = 127.0f / 6.0f, ss = SXQ;
        #pragma unroll 1
        for (int cb = 0; cb < 4; cb++) {
            const int col = cb * 32 + j;
            const int colE = (bx & 7) * 128 + col;
            union { int8_t b[16]; uint4 v; } Uh, Ul;
            #pragma unroll
            for (int i = 0; i < 16; i++)
                q8pair(stg[(rs * 16 + i) * 132 + col], ss, invs, Uh.b[i], Ul.b[i]);
            const size_t off = ((size_t)bidx * 1024 + colE) * 2048 + s0 + rs * 16;
            *(uint4*)(vth8 + off) = Uh.v;
            *(uint4*)(vtl8 + off) = Ul.v;
        }
    }
}

// ---------------------------------------------------------------------------
// bf16x3 GEMM NT for out-proj: out = ctx @ W_out^T + b  (fp32 out)
// ---------------------------------------------------------------------------
__global__ void __launch_bounds__(256, 2)
gemm3_k(const __nv_bfloat16* __restrict__ Ah, const __nv_bfloat16* __restrict__ Al,
        const __nv_bfloat16* __restrict__ Bh, const __nv_bfloat16* __restrict__ Bl,
        int K, float* __restrict__ outF, const float* __restrict__ bias)
{
    extern __shared__ char dsm[];
    const uint32_t sb0 = smem_u32(dsm);
    const uint32_t SB  = (sb0 + 127u) & ~127u;
    float* stg = (float*)(dsm + (SB - sb0));

    const int tid  = threadIdx.x;
    const int wid  = tid >> 5, lane = tid & 31;
    const int wm   = wid >> 2, wn = wid & 3;
    const int bx = blockIdx.x, by = blockIdx.y;

    const char* baseA_h = (const char*)(Ah + (size_t)by * 128 * EMB);
    const char* baseA_l = (const char*)(Al + (size_t)by * 128 * EMB);
    const char* baseB_h = (const char*)(Bh + (size_t)bx * 128 * EMB);
    const char* baseB_l = (const char*)(Bl + (size_t)bx * 128 * EMB);
    const size_t str = (size_t)EMB * 2;

    auto load_chunk = [&](int c, int s) {
        const uint32_t stb = SB + (uint32_t)s * STAGE16;
        #pragma unroll
        for (int i = 0; i < 8; i++) {
            const int id = i * 256 + tid;
            const int tt = id >> 9;
            const int u  = id & 511;
            const int r  = u >> 2;
            const int c16 = u & 3;
            const char* base = (tt == 0) ? baseA_h : (tt == 1) ? baseA_l
                             : (tt == 2) ? baseB_h : baseB_l;
            const char* src = base + (size_t)r * str + (size_t)c * 64 + (size_t)c16 * 16;
            const uint32_t dst = stb + (uint32_t)tt * TILE16 + (uint32_t)(r * ROWB16 + c16 * 16);
            CP16(dst, src);
        }
        CP_COMMIT();
    };

    float d[4][4][4];
    #pragma unroll
    for (int a = 0; a < 4; a++)
        #pragma unroll
        for (int b = 0; b < 4; b++)
            #pragma unroll
            for (int e = 0; e < 4; e++) d[a][b][e] = 0.0f;

    const int NC = K >> 5;
    load_chunk(0, 0);

    const uint32_t offA = (uint32_t)((wm * 64 + (lane & 7) + ((lane >> 3) & 1) * 8) * ROWB16
                                     + ((lane >> 4) & 1) * 16);
    const uint32_t offB = (uint32_t)((wn * 32 + ((lane >> 4) & 1) * 8 + (lane & 7)) * ROWB16
                                     + ((lane >> 3) & 1) * 16);

    for (int c = 0; c < NC; c++) {
        CP_WAIT0();
        __syncthreads();
        const int s = c & 1;
        if (c + 1 < NC) load_chunk(c + 1, s ^ 1);

        const uint32_t stb = SB + (uint32_t)s * STAGE16;
        const uint32_t Ah_s = stb,             Al_s = stb + TILE16;
        const uint32_t Bh_s = stb + 2*TILE16,  Bl_s = stb + 3*TILE16;

        #pragma unroll
        for (int kk = 0; kk < 2; kk++) {
            uint32_t bh[8], bl[8];
            ldsm4(&bh[0], Bh_s + offB + (uint32_t)(kk * 32));
            ldsm4(&bh[4], Bh_s + offB + (uint32_t)(16 * ROWB16 + kk * 32));
            ldsm4(&bl[0], Bl_s + offB + (uint32_t)(kk * 32));
            ldsm4(&bl[4], Bl_s + offB + (uint32_t)(16 * ROWB16 + kk * 32));
            #pragma unroll
            for (int mt = 0; mt < 4; mt++) {
                uint32_t ah[4], al[4];
                const uint32_t o = (uint32_t)(mt * 16 * ROWB16) + (uint32_t)(kk * 32);
                ldsm4(ah, Ah_s + offA + o);
                ldsm4(al, Al_s + offA + o);
                #pragma unroll
                for (int nt = 0; nt < 4; nt++) {
                    mma16816(d[mt][nt], ah, &bh[nt * 2]);
                    mma16816(d[mt][nt], ah, &bl[nt * 2]);
                    mma16816(d[mt][nt], al, &bh[nt * 2]);
                }
            }
        }
    }
    __syncthreads();

    #pragma unroll
    for (int mt = 0; mt < 4; mt++) {
        #pragma unroll
        for (int nt = 0; nt < 4; nt++) {
            const int r0 = wm * 64 + mt * 16 + (lane >> 2);
            const int c0 = wn * 32 + nt * 8 + (lane & 3) * 2;
            #pragma unroll
            for (int h = 0; h < 2; h++) {
                float v0 = d[mt][nt][h * 2 + 0] + bias[bx * 128 + c0];
                float v1 = d[mt][nt][h * 2 + 1] + bias[bx * 128 + c0 + 1];
                *(float2*)&stg[(r0 + h * 8) * 132 + c0] = make_float2(v0, v1);
            }
        }
    }
    __syncthreads();

    const int row = tid >> 1, h = tid & 1;
    float* dst = outF + ((size_t)by * 128 + row) * EMB + (size_t)bx * 128 + h * 64;
    #pragma unroll
    for (int q = 0; q < 16; q++) {
        float4 v;
        v.x = stg[row * 132 + h * 64 + q * 4 + 0];
        v.y = stg[row * 132 + h * 64 + q * 4 + 1];
        v.z = stg[row * 132 + h * 64 + q * 4 + 2];
        v.w = stg[row * 132 + h * 64 + q * 4 + 3];
        ((float4*)dst)[q] = v;
    }
}

// ---------------------------------------------------------------------------
// Input conversion: X -> int8 limbs, W_qkv -> int8 limbs, W_out -> bf16 hi/lo
// ---------------------------------------------------------------------------
__global__ void conv_all(const float4* __restrict__ X,  int8_t* __restrict__ Xh,  int8_t* __restrict__ Xl,  int n1,
                         const float4* __restrict__ Wq, int8_t* __restrict__ Wqh, int8_t* __restrict__ Wql, int n2,
                         const float4* __restrict__ Wo, __nv_bfloat16* __restrict__ Woh, __nv_bfloat16* __restrict__ Wol, int n3)
{
    int i = blockIdx.x * 256 + threadIdx.x;
    if (i < n1 + n2) {
        const float4* src; int8_t *h, *l; float s, invs;
        if (i < n1) { src = X;  h = Xh;  l = Xl;  s = SXQ; invs = 127.0f/6.0f; }
        else        { src = Wq; h = Wqh; l = Wql; s = SWQ; invs = 127.0f/0.2f; i -= n1; }
        const float4 v = src[i];
        const float vv[4] = {v.x, v.y, v.z, v.w};
        union { int8_t b[4]; uint32_t u; } H, L;
        #pragma unroll
        for (int k = 0; k < 4; k++) q8pair(vv[k], s, invs, H.b[k], L.b[k]);
        *(uint32_t*)(h + (size_t)i * 4) = H.u;
        *(uint32_t*)(l + (size_t)i * 4) = L.u;
    } else if (i < n1 + n2 + n3) {
        i -= n1 + n2;
        const float4 v = Wo[i];
        const float vv[4] = {v.x, v.y, v.z, v.w};
        union { __nv_bfloat16 b[4]; uint2 u; } H, L;
        #pragma unroll
        for (int k = 0; k < 4; k++) {
            __nv_bfloat16 hi = __float2bfloat16(vv[k]);
            H.b[k] = hi;
            L.b[k] = __float2bfloat16(vv[k] - __bfloat162float(hi));
        }
        *(uint2*)(Woh + (size_t)i * 4) = H.u;
        *(uint2*)(Wol + (size_t)i * 4) = L.u;
    }
}

// ---------------------------------------------------------------------------
// Masked softmax; emits int8 limbs with per-row scale. Vectorized.
// ---------------------------------------------------------------------------
__global__ void __launch_bounds__(256)
softmax_k(const float* __restrict__ att, const int* __restrict__ mask,
          int8_t* __restrict__ oh, int8_t* __restrict__ ol,
          float* __restrict__ rowscale)
{
    const size_t row = blockIdx.x;
    const float4* a4 = (const float4*)(att  + row * (size_t)SLEN);
    const int4*   m4 = (const int4*)  (mask + row * (size_t)SLEN);
    const int tid = threadIdx.x;

    float v[8];
    const float4 x0 = a4[tid], x1 = a4[tid + 256];
    const int4   q0 = m4[tid], q1 = m4[tid + 256];
    v[0] = q0.x ? x0.x : -INFINITY;
    v[1] = q0.y ? x0.y : -INFINITY;
    v[2] = q0.z ? x0.z : -INFINITY;
    v[3] = q0.w ? x0.w : -INFINITY;
    v[4] = q1.x ? x1.x : -INFINITY;
    v[5] = q1.y ? x1.y : -INFINITY;
    v[6] = q1.z ? x1.z : -INFINITY;
    v[7] = q1.w ? x1.w : -INFINITY;

    float lmax = v[0];
    #pragma unroll
    for (int i = 1; i < 8; i++) lmax = fmaxf(lmax, v[i]);

    __shared__ float smax[8], ssum[8];
    #pragma unroll
    for (int o = 16; o > 0; o >>= 1)
        lmax = fmaxf(lmax, __shfl_xor_sync(0xffffffffu, lmax, o));
    if ((tid & 31) == 0) smax[tid >> 5] = lmax;
    __syncthreads();
    const float gmax = fmaxf(fmaxf(fmaxf(smax[0], smax[1]), fmaxf(smax[2], smax[3])),
                             fmaxf(fmaxf(smax[4], smax[5]), fmaxf(smax[6], smax[7])));
    float lsum = 0.0f;
    #pragma unroll
    for (int i = 0; i < 8; i++) { v[i] = __expf(v[i] - gmax); lsum += v[i]; }
    #pragma unroll
    for (int o = 16; o > 0; o >>= 1)
        lsum += __shfl_xor_sync(0xffffffffu, lsum, o);
    if ((tid & 31) == 0) ssum[tid >> 5] = lsum;
    __syncthreads();
    const float gsum = (ssum[0] + ssum[1]) + (ssum[2] + ssum[3])
                     + (ssum[4] + ssum[5]) + (ssum[6] + ssum[7]);
    const float inv = 1.0f / gsum;        // = p_max (max exp term is 1)

    // p = v[i]*inv; row scale sR = inv/127  =>  p/sR = 127*v[i]  (v in [0,1])
    if (tid == 0) rowscale[row] = inv * (1.0f / 127.0f);

    union { int8_t b[4]; uint32_t u; } H0, L0, H1, L1;
    #pragma unroll
    for (int i = 0; i < 4; i++) {
        const float t = v[i] * 127.0f;
        const float hf = rintf(t);
        H0.b[i] = (int8_t)hf;
        L0.b[i] = (int8_t)rintf((t - hf) * 128.0f);
    }
    #pragma unroll
    for (int i = 0; i < 4; i++) {
        const float t = v[4 + i] * 127.0f;
        const float hf = rintf(t);
        H1.b[i] = (int8_t)hf;
        L1.b[i] = (int8_t)rintf((t - hf) * 128.0f);
    }
    const size_t base = row * (size_t)SLEN;
    *(uint32_t*)(oh + base + tid * 4)        = H0.u;
    *(uint32_t*)(ol + base + tid * 4)        = L0.u;
    *(uint32_t*)(oh + base + 1024 + tid * 4) = H1.u;
    *(uint32_t*)(ol + base + 1024 + tid * 4) = L1.u;
}

// ---------------------------------------------------------------------------
extern "C" void kernel_launch(void* const* d_in, const int* in_sizes, int n_in,
                              void* d_out, int out_size)
{
    const float* X     = (const float*)d_in[0];
    const int*   mask  = (const int*)  d_in[1];
    const float* W_qkv = (const float*)d_in[2];
    const float* b_qkv = (const float*)d_in[3];
    const float* W_out = (const float*)d_in[4];
    const float* b_out = (const float*)d_in[5];
    float*       out   = (float*)d_out;

    int8_t *X8h, *X8l, *Wq8h, *Wq8l, *q8h, *q8l, *k8h, *k8l, *v8th, *v8tl, *at8h, *at8l;
    __nv_bfloat16 *Woh, *Wol, *ch, *cl;
    float *att, *rs;
    cudaGetSymbolAddress((void**)&X8h,  g_X8h);  cudaGetSymbolAddress((void**)&X8l,  g_X8l);
    cudaGetSymbolAddress((void**)&Wq8h, g_Wq8h); cudaGetSymbolAddress((void**)&Wq8l, g_Wq8l);
    cudaGetSymbolAddress((void**)&Woh,  g_Woh);  cudaGetSymbolAddress((void**)&Wol,  g_Wol);
    cudaGetSymbolAddress((void**)&q8h,  g_q8h);  cudaGetSymbolAddress((void**)&q8l,  g_q8l);
    cudaGetSymbolAddress((void**)&k8h,  g_k8h);  cudaGetSymbolAddress((void**)&k8l,  g_k8l);
    cudaGetSymbolAddress((void**)&v8th, g_v8th); cudaGetSymbolAddress((void**)&v8tl, g_v8tl);
    cudaGetSymbolAddress((void**)&att,  g_att);
    cudaGetSymbolAddress((void**)&at8h, g_at8h); cudaGetSymbolAddress((void**)&at8l, g_at8l);
    cudaGetSymbolAddress((void**)&rs,   g_rs);
    cudaGetSymbolAddress((void**)&ch,   g_ch);   cudaGetSymbolAddress((void**)&cl,   g_cl);

    cudaFuncSetAttribute(igemm_k<0>, cudaFuncAttributeMaxDynamicSharedMemorySize, IG_SMEM);
    cudaFuncSetAttribute(igemm_k<1>, cudaFuncAttributeMaxDynamicSharedMemorySize, IG_SMEM);
    cudaFuncSetAttribute(igemm_k<2>, cudaFuncAttributeMaxDynamicSharedMemorySize, IG_SMEM);
    cudaFuncSetAttribute(gemm3_k,    cudaFuncAttributeMaxDynamicSharedMemorySize, G16_SMEM);

    // Convert inputs
    {
        const int n1 = BATCH*SLEN*EMB/4, n2 = QKVF*EMB/4, n3 = EMB*EMB/4;
        conv_all<<<(n1 + n2 + n3 + 255)/256, 256>>>(
            (const float4*)X, X8h, X8l, n1,
            (const float4*)W_qkv, Wq8h, Wq8l, n2,
            (const float4*)W_out, Woh, Wol, n3);
    }

    const float s_qkv = SXQ * SWQ;
    const float s_att = SXQ * SXQ * (1.0f / 32.0f);

    // 1) qkv = X @ W_qkv^T + b  -> q/k int8 limbs, V^T int8 limbs
    igemm_k<0><<<dim3(QKVF/128, (BATCH*SLEN)/128, 1), 256, IG_SMEM>>>(
        X8h, X8l, 0, EMB, Wq8h, Wq8l, 0, EMB, EMB, s_qkv,
        nullptr, 0, 0, q8h, q8l, k8h, k8l, v8th, v8tl,
        nullptr, nullptr, nullptr, b_qkv);

    // 2) att = (Q @ K^T) / 32   (fp32, per batch)
    igemm_k<1><<<dim3(SLEN/128, SLEN/128, BATCH), 256, IG_SMEM>>>(
        q8h, q8l, (size_t)SLEN*EMB, EMB, k8h, k8l, (size_t)SLEN*EMB, EMB, EMB, s_att,
        att, (size_t)SLEN*SLEN, SLEN,
        nullptr, nullptr, nullptr, nullptr, nullptr, nullptr,
        nullptr, nullptr, nullptr, nullptr);

    // 3) masked softmax -> att int8 limbs + row scales
    softmax_k<<<BATCH*SLEN, 256>>>(att, mask, at8h, at8l, rs);

    // 4) ctx = att @ V  (B = V^T, NT)  -> ctx bf16 hi/lo
    igemm_k<2><<<dim3(EMB/128, SLEN/128, BATCH), 256, IG_SMEM>>>(
        at8h, at8l, (size_t)SLEN*SLEN, SLEN, v8th, v8tl, (size_t)EMB*SLEN, SLEN, SLEN,
        SXQ,
        nullptr, 0, 0, nullptr, nullptr, nullptr, nullptr, nullptr, nullptr,
        ch, cl, rs, nullptr);

    // 5) out = ctx @ W_out^T + b   (bf16x3)
    gemm3_k<<<dim3(EMB/128, (BATCH*SLEN)/128, 1), 256, G16_SMEM>>>(
        ch, cl, Woh, Wol, EMB, out, b_out);
}

// round 10
// speedup vs baseline: 2.8641x; 2.8641x over previous
#include <cuda_runtime.h>
#include <cuda_bf16.h>
#include <cuda_fp16.h>
#include <math.h>
#include <stdint.h>

// Problem constants
#define BATCH 4
#define SLEN  2048
#define EMB   1024
#define QKVF  3072

// ---------------------------------------------------------------------------
// Device scratch (allocation-free rule: __device__ globals)
// ---------------------------------------------------------------------------
__device__ __align__(256) __nv_bfloat16 g_Xh[(size_t)BATCH*SLEN*EMB];
__device__ __align__(256) __nv_bfloat16 g_Xl[(size_t)BATCH*SLEN*EMB];
__device__ __align__(256) __nv_bfloat16 g_Wqh[(size_t)QKVF*EMB];
__device__ __align__(256) __nv_bfloat16 g_Wql[(size_t)QKVF*EMB];
__device__ __align__(256) __nv_bfloat16 g_Woh[(size_t)EMB*EMB];
__device__ __align__(256) __nv_bfloat16 g_Wol[(size_t)EMB*EMB];
__device__ __align__(256) __half g_qf [(size_t)BATCH*SLEN*EMB];   // q single fp16
__device__ __align__(256) __half g_kfh[(size_t)BATCH*SLEN*EMB];   // k fp16 hi
__device__ __align__(256) __half g_kfl[(size_t)BATCH*SLEN*EMB];   // k fp16 lo
__device__ __align__(256) __half g_vtf[(size_t)BATCH*EMB*SLEN];   // V^T single fp16
__device__ __align__(256) float  g_att[(size_t)BATCH*SLEN*SLEN];
__device__ __align__(256) __half g_athf[(size_t)BATCH*SLEN*SLEN]; // att fp16 hi
__device__ __align__(256) __half g_atlf[(size_t)BATCH*SLEN*SLEN]; // att fp16 lo
__device__ __align__(256) __nv_bfloat16 g_ch[(size_t)BATCH*SLEN*EMB];
__device__ __align__(256) __nv_bfloat16 g_cl[(size_t)BATCH*SLEN*EMB];

// ---------------------------------------------------------------------------
// PTX helpers (sm_80+ only — tcgen05 rejected by compute_103 PTX target)
// ---------------------------------------------------------------------------
__device__ __forceinline__ uint32_t smem_u32(const void* p) {
    uint32_t a;
    asm("{ .reg .u64 t; cvta.to.shared.u64 t, %1; cvt.u32.u64 %0, t; }"
        : "=r"(a) : "l"(p));
    return a;
}
#define CP16(d, s)   asm volatile("cp.async.cg.shared.global [%0], [%1], 16;" :: "r"(d), "l"(s))
#define CP_COMMIT()  asm volatile("cp.async.commit_group;" ::: "memory")
#define CP_WAIT0()   asm volatile("cp.async.wait_group 0;" ::: "memory")

__device__ __forceinline__ void ldsm4(uint32_t* r, uint32_t addr) {
    asm volatile("ldmatrix.sync.aligned.m8n8.x4.shared.b16 {%0,%1,%2,%3}, [%4];"
        : "=r"(r[0]), "=r"(r[1]), "=r"(r[2]), "=r"(r[3]) : "r"(addr));
}
__device__ __forceinline__ void mma16816(float* d, const uint32_t* a, const uint32_t* b) {
    asm volatile("mma.sync.aligned.m16n8k16.row.col.f32.bf16.bf16.f32 "
        "{%0,%1,%2,%3}, {%4,%5,%6,%7}, {%8,%9}, {%0,%1,%2,%3};"
        : "+f"(d[0]), "+f"(d[1]), "+f"(d[2]), "+f"(d[3])
        : "r"(a[0]), "r"(a[1]), "r"(a[2]), "r"(a[3]), "r"(b[0]), "r"(b[1]));
}
__device__ __forceinline__ void hmma16816(float* d, const uint32_t* a, const uint32_t* b) {
    asm volatile("mma.sync.aligned.m16n8k16.row.col.f32.f16.f16.f32 "
        "{%0,%1,%2,%3}, {%4,%5,%6,%7}, {%8,%9}, {%0,%1,%2,%3};"
        : "+f"(d[0]), "+f"(d[1]), "+f"(d[2]), "+f"(d[3])
        : "r"(a[0]), "r"(a[1]), "r"(a[2]), "r"(a[3]), "r"(b[0]), "r"(b[1]));
}

// ---- bf16x3 tiling: CTA 128x128, BK=32, 8 warps (2x4), 2 CTAs/SM ----
#define ROWB    80
#define TILEB   (128 * ROWB)
#define STAGEB  (4 * TILEB)
#define GEMM_SMEM (2 * STAGEB + 128)

// ---- fp16 2-MMA tiling: CTA 128x128, BK=64, 3 tiles/stage, 2 CTAs/SM ----
#define HROWB   144
#define HTILE   (128 * HROWB)
#define HSTAGE  (3 * HTILE)
#define HG_SMEM (2 * HSTAGE + 128)   // 110720 B

// ===========================================================================
// gemm0: bf16x3 NT  qkv = X @ Wqkv^T + b ; emit q (fp16), k (fp16 hi/lo),
// V^T (fp16, transposed)
// ===========================================================================
__global__ void __launch_bounds__(256, 2)
gemm0_k(const __nv_bfloat16* __restrict__ Ah, const __nv_bfloat16* __restrict__ Al,
        const __nv_bfloat16* __restrict__ Bh, const __nv_bfloat16* __restrict__ Bl,
        const float* __restrict__ bias,
        __half* __restrict__ qf, __half* __restrict__ kfh, __half* __restrict__ kfl,
        __half* __restrict__ vtf)
{
    extern __shared__ char dsm[];
    const uint32_t sb0 = smem_u32(dsm);
    const uint32_t SB  = (sb0 + 127u) & ~127u;
    float* stg = (float*)(dsm + (SB - sb0));

    const int tid  = threadIdx.x;
    const int wid  = tid >> 5, lane = tid & 31;
    const int wm   = wid >> 2, wn = wid & 3;
    const int bx = blockIdx.x, by = blockIdx.y;

    const char* baseA_h = (const char*)(Ah + (size_t)by * 128 * EMB);
    const char* baseA_l = (const char*)(Al + (size_t)by * 128 * EMB);
    const char* baseB_h = (const char*)(Bh + (size_t)bx * 128 * EMB);
    const char* baseB_l = (const char*)(Bl + (size_t)bx * 128 * EMB);
    const size_t str = (size_t)EMB * 2;

    auto load_chunk = [&](int c, int s) {
        const uint32_t stb = SB + (uint32_t)s * STAGEB;
        #pragma unroll
        for (int i = 0; i < 8; i++) {
            const int id = i * 256 + tid;
            const int t  = id >> 9;
            const int u  = id & 511;
            const int r  = u >> 2;
            const int c16 = u & 3;
            const char* base = (t == 0) ? baseA_h : (t == 1) ? baseA_l
                             : (t == 2) ? baseB_h : baseB_l;
            const char* src = base + (size_t)r * str + (size_t)c * 64 + (size_t)c16 * 16;
            const uint32_t dst = stb + (uint32_t)t * TILEB + (uint32_t)(r * ROWB + c16 * 16);
            CP16(dst, src);
        }
        CP_COMMIT();
    };

    float d[4][4][4];
    #pragma unroll
    for (int a = 0; a < 4; a++)
        #pragma unroll
        for (int b = 0; b < 4; b++)
            #pragma unroll
            for (int e = 0; e < 4; e++) d[a][b][e] = 0.0f;

    const int NC = EMB >> 5;
    load_chunk(0, 0);

    const uint32_t offA = (uint32_t)((wm * 64 + (lane & 7) + ((lane >> 3) & 1) * 8) * ROWB
                                     + ((lane >> 4) & 1) * 16);
    const uint32_t offB = (uint32_t)((wn * 32 + ((lane >> 4) & 1) * 8 + (lane & 7)) * ROWB
                                     + ((lane >> 3) & 1) * 16);

    for (int c = 0; c < NC; c++) {
        CP_WAIT0();
        __syncthreads();
        const int s = c & 1;
        if (c + 1 < NC) load_chunk(c + 1, s ^ 1);

        const uint32_t stb = SB + (uint32_t)s * STAGEB;
        const uint32_t Ah_s = stb,            Al_s = stb + TILEB;
        const uint32_t Bh_s = stb + 2*TILEB,  Bl_s = stb + 3*TILEB;

        #pragma unroll
        for (int kk = 0; kk < 2; kk++) {
            uint32_t bh[8], bl[8];
            ldsm4(&bh[0], Bh_s + offB + (uint32_t)(kk * 32));
            ldsm4(&bh[4], Bh_s + offB + (uint32_t)(16 * ROWB + kk * 32));
            ldsm4(&bl[0], Bl_s + offB + (uint32_t)(kk * 32));
            ldsm4(&bl[4], Bl_s + offB + (uint32_t)(16 * ROWB + kk * 32));
            #pragma unroll
            for (int mt = 0; mt < 4; mt++) {
                uint32_t ah[4], al[4];
                const uint32_t o = (uint32_t)(mt * 16 * ROWB) + (uint32_t)(kk * 32);
                ldsm4(ah, Ah_s + offA + o);
                ldsm4(al, Al_s + offA + o);
                #pragma unroll
                for (int nt = 0; nt < 4; nt++) {
                    mma16816(d[mt][nt], ah, &bh[nt * 2]);
                    mma16816(d[mt][nt], ah, &bl[nt * 2]);
                    mma16816(d[mt][nt], al, &bh[nt * 2]);
                }
            }
        }
    }
    __syncthreads();

    // accumulators -> smem staging (+bias)
    #pragma unroll
    for (int mt = 0; mt < 4; mt++) {
        #pragma unroll
        for (int nt = 0; nt < 4; nt++) {
            const int r0 = wm * 64 + mt * 16 + (lane >> 2);
            const int c0 = wn * 32 + nt * 8 + (lane & 3) * 2;
            #pragma unroll
            for (int h = 0; h < 2; h++) {
                float v0 = d[mt][nt][h * 2 + 0] + bias[bx * 128 + c0];
                float v1 = d[mt][nt][h * 2 + 1] + bias[bx * 128 + c0 + 1];
                *(float2*)&stg[(r0 + h * 8) * 132 + c0] = make_float2(v0, v1);
            }
        }
    }
    __syncthreads();

    if (bx < 8) {            // q -> single fp16
        #pragma unroll 1
        for (int cb = 0; cb < 4; cb++) {
            #pragma unroll 1
            for (int it = 0; it < 2; it++) {
                const int row = it * 64 + (tid >> 2);
                const int qq  = tid & 3;
                const int col = cb * 32 + qq * 8;
                const size_t rg = (size_t)by * 128 + row;
                union { __half h[8]; uint4 v; } U;
                #pragma unroll
                for (int i = 0; i < 8; i++)
                    U.h[i] = __float2half(stg[row * 132 + col + i]);
                *(uint4*)(qf + rg * 1024 + bx * 128 + col) = U.v;
            }
        }
    } else if (bx < 16) {    // k -> fp16 hi/lo
        #pragma unroll 1
        for (int cb = 0; cb < 4; cb++) {
            #pragma unroll 1
            for (int it = 0; it < 2; it++) {
                const int row = it * 64 + (tid >> 2);
                const int qq  = tid & 3;
                const int col = cb * 32 + qq * 8;
                const size_t rg = (size_t)by * 128 + row;
                union { __half h[8]; uint4 v; } Uh, Ul;
                #pragma unroll
                for (int i = 0; i < 8; i++) {
                    float v = stg[row * 132 + col + i];
                    __half hi = __float2half(v);
                    Uh.h[i] = hi;
                    Ul.h[i] = __float2half(v - __half2float(hi));
                }
                const size_t off = rg * 1024 + (bx - 8) * 128 + col;
                *(uint4*)(kfh + off) = Uh.v;
                *(uint4*)(kfl + off) = Ul.v;
            }
        }
    } else {                 // V^T single fp16, transposed to vt[b][e][s]
        const int j  = tid >> 3;
        const int rs = tid & 7;
        const int bidx = by >> 4;
        const int s0 = (by * 128) & 2047;
        #pragma unroll 1
        for (int cb = 0; cb < 4; cb++) {
            const int col = cb * 32 + j;
            const int colE = (bx - 16) * 128 + col;
            union { __half h[16]; uint4 v[2]; } U;
            #pragma unroll
            for (int i = 0; i < 16; i++)
                U.h[i] = __float2half(stg[(rs * 16 + i) * 132 + col]);
            const size_t off = ((size_t)bidx * 1024 + colE) * 2048 + s0 + rs * 16;
            *(uint4*)(vtf + off)     = U.v[0];
            *(uint4*)(vtf + off + 8) = U.v[1];
        }
    }
}

// ===========================================================================
// hgemm: fp16 one-side-exact, 2 MMAs.  D[m,n] = alpha * sum_k A[m,k]B[n,k]
// MODE 1 (scores): A = Sg (q, single), B = S0/S1 (k hi/lo); fp32 out.
// MODE 2 (ctx):    A = S0/S1 (att hi/lo), B = Sg (V^T, single); bf16 hi/lo out.
// ===========================================================================
template<int MODE>
__global__ void __launch_bounds__(256, 2)
hgemm_k(const __half* __restrict__ S0, const __half* __restrict__ S1,
        const __half* __restrict__ Sg,
        size_t sS, int ldS, size_t sG, int ldG, int K, float alpha,
        float* __restrict__ outF, size_t sF, int ldF,
        __nv_bfloat16* __restrict__ ch, __nv_bfloat16* __restrict__ cl)
{
    extern __shared__ char dsm[];
    const uint32_t sb0 = smem_u32(dsm);
    const uint32_t SB  = (sb0 + 127u) & ~127u;
    float* stg = (float*)(dsm + (SB - sb0));

    const int tid  = threadIdx.x;
    const int wid  = tid >> 5, lane = tid & 31;
    const int wm   = wid >> 2, wn = wid & 3;    // warp 64x32
    const int bx = blockIdx.x, by = blockIdx.y, z = blockIdx.z;

    const int splitRow  = (MODE == 2 ? by : bx) * 128;
    const int singleRow = (MODE == 2 ? bx : by) * 128;
    const char* b0 = (const char*)(S0 + (size_t)z * sS + (size_t)splitRow * ldS);
    const char* b1 = (const char*)(S1 + (size_t)z * sS + (size_t)splitRow * ldS);
    const char* bg = (const char*)(Sg + (size_t)z * sG + (size_t)singleRow * ldG);
    const size_t strS = (size_t)ldS * 2, strG = (size_t)ldG * 2;

    auto load_chunk = [&](int c, int s) {
        const uint32_t stb = SB + (uint32_t)s * HSTAGE;
        #pragma unroll
        for (int i = 0; i < 12; i++) {
            const int id = i * 256 + tid;       // 0..3071
            const int t  = id >> 10;            // tile 0..2
            const int u  = id & 1023;
            const int r  = u >> 3;              // row 0..127
            const int c16 = u & 7;              // 16B piece 0..7
            const char* base = (t == 0) ? b0 : (t == 1) ? b1 : bg;
            const size_t str = (t < 2) ? strS : strG;
            const char* src = base + (size_t)r * str + (size_t)c * 128 + (size_t)c16 * 16;
            const uint32_t dst = stb + (uint32_t)t * HTILE + (uint32_t)(r * HROWB + c16 * 16);
            CP16(dst, src);
        }
        CP_COMMIT();
    };

    float d[4][4][4];
    #pragma unroll
    for (int a = 0; a < 4; a++)
        #pragma unroll
        for (int b = 0; b < 4; b++)
            #pragma unroll
            for (int e = 0; e < 4; e++) d[a][b][e] = 0.0f;

    const int NC = K >> 6;
    load_chunk(0, 0);

    const uint32_t offA = (uint32_t)((wm * 64 + (lane & 7) + ((lane >> 3) & 1) * 8) * HROWB
                                     + ((lane >> 4) & 1) * 16);
    const uint32_t offB = (uint32_t)((wn * 32 + ((lane >> 4) & 1) * 8 + (lane & 7)) * HROWB
                                     + ((lane >> 3) & 1) * 16);

    for (int c = 0; c < NC; c++) {
        CP_WAIT0();
        __syncthreads();
        const int s = c & 1;
        if (c + 1 < NC) load_chunk(c + 1, s ^ 1);

        const uint32_t stb = SB + (uint32_t)s * HSTAGE;

        if (MODE == 1) {     // split B (kh, kl), single A (q)
            const uint32_t Bh_s = stb, Bl_s = stb + HTILE, A_s = stb + 2 * HTILE;
            #pragma unroll
            for (int kk = 0; kk < 4; kk++) {
                uint32_t p0[8], p1[8];
                ldsm4(&p0[0], Bh_s + offB + (uint32_t)(kk * 32));
                ldsm4(&p0[4], Bh_s + offB + (uint32_t)(16 * HROWB + kk * 32));
                ldsm4(&p1[0], Bl_s + offB + (uint32_t)(kk * 32));
                ldsm4(&p1[4], Bl_s + offB + (uint32_t)(16 * HROWB + kk * 32));
                #pragma unroll
                for (int mt = 0; mt < 4; mt++) {
                    uint32_t a[4];
                    ldsm4(a, A_s + offA + (uint32_t)(mt * 16 * HROWB + kk * 32));
                    #pragma unroll
                    for (int nt = 0; nt < 4; nt++) {
                        hmma16816(d[mt][nt], a, &p0[nt * 2]);
                        hmma16816(d[mt][nt], a, &p1[nt * 2]);
                    }
                }
            }
        } else {             // split A (att hi/lo), single B (V^T)
            const uint32_t Ah_s = stb, Al_s = stb + HTILE, B_s = stb + 2 * HTILE;
            #pragma unroll
            for (int kk = 0; kk < 4; kk++) {
                uint32_t bq[8];
                ldsm4(&bq[0], B_s + offB + (uint32_t)(kk * 32));
                ldsm4(&bq[4], B_s + offB + (uint32_t)(16 * HROWB + kk * 32));
                #pragma unroll
                for (int mt = 0; mt < 4; mt++) {
                    uint32_t ah[4], al[4];
                    const uint32_t o = (uint32_t)(mt * 16 * HROWB + kk * 32);
                    ldsm4(ah, Ah_s + offA + o);
                    ldsm4(al, Al_s + offA + o);
                    #pragma unroll
                    for (int nt = 0; nt < 4; nt++) {
                        hmma16816(d[mt][nt], ah, &bq[nt * 2]);
                        hmma16816(d[mt][nt], al, &bq[nt * 2]);
                    }
                }
            }
        }
    }
    __syncthreads();

    #pragma unroll
    for (int mt = 0; mt < 4; mt++) {
        #pragma unroll
        for (int nt = 0; nt < 4; nt++) {
            const int r0 = wm * 64 + mt * 16 + (lane >> 2);
            const int c0 = wn * 32 + nt * 8 + (lane & 3) * 2;
            #pragma unroll
            for (int h = 0; h < 2; h++) {
                float v0 = d[mt][nt][h * 2 + 0] * alpha;
                float v1 = d[mt][nt][h * 2 + 1] * alpha;
                *(float2*)&stg[(r0 + h * 8) * 132 + c0] = make_float2(v0, v1);
            }
        }
    }
    __syncthreads();

    if (MODE == 1) {
        const int row = tid >> 1, h = tid & 1;
        float* dst = outF + (size_t)z * sF + ((size_t)by * 128 + row) * ldF
                   + (size_t)bx * 128 + h * 64;
        #pragma unroll
        for (int q = 0; q < 16; q++) {
            float4 v;
            v.x = stg[row * 132 + h * 64 + q * 4 + 0];
            v.y = stg[row * 132 + h * 64 + q * 4 + 1];
            v.z = stg[row * 132 + h * 64 + q * 4 + 2];
            v.w = stg[row * 132 + h * 64 + q * 4 + 3];
            ((float4*)dst)[q] = v;
        }
    } else {
        #pragma unroll 1
        for (int cb = 0; cb < 4; cb++) {
            #pragma unroll 1
            for (int it = 0; it < 2; it++) {
                const int row = it * 64 + (tid >> 2);
                const int qq  = tid & 3;
                const int col = cb * 32 + qq * 8;
                const size_t rg = (size_t)z * SLEN + (size_t)by * 128 + row;
                union { __nv_bfloat16 b[8]; uint4 v; } Uh, Ul;
                #pragma unroll
                for (int i = 0; i < 8; i++) {
                    float v = stg[row * 132 + col + i];
                    __nv_bfloat16 hi = __float2bfloat16(v);
                    Uh.b[i] = hi;
                    Ul.b[i] = __float2bfloat16(v - __bfloat162float(hi));
                }
                const size_t off = rg * 1024 + bx * 128 + col;
                *(uint4*)(ch + off) = Uh.v;
                *(uint4*)(cl + off) = Ul.v;
            }
        }
    }
}

// ===========================================================================
// gemm3: bf16x3 NT  out = ctx @ W_out^T + b  (fp32 out)
// ===========================================================================
__global__ void __launch_bounds__(256, 2)
gemm3_k(const __nv_bfloat16* __restrict__ Ah, const __nv_bfloat16* __restrict__ Al,
        const __nv_bfloat16* __restrict__ Bh, const __nv_bfloat16* __restrict__ Bl,
        float* __restrict__ outF, const float* __restrict__ bias)
{
    extern __shared__ char dsm[];
    const uint32_t sb0 = smem_u32(dsm);
    const uint32_t SB  = (sb0 + 127u) & ~127u;
    float* stg = (float*)(dsm + (SB - sb0));

    const int tid  = threadIdx.x;
    const int wid  = tid >> 5, lane = tid & 31;
    const int wm   = wid >> 2, wn = wid & 3;
    const int bx = blockIdx.x, by = blockIdx.y;

    const char* baseA_h = (const char*)(Ah + (size_t)by * 128 * EMB);
    const char* baseA_l = (const char*)(Al + (size_t)by * 128 * EMB);
    const char* baseB_h = (const char*)(Bh + (size_t)bx * 128 * EMB);
    const char* baseB_l = (const char*)(Bl + (size_t)bx * 128 * EMB);
    const size_t str = (size_t)EMB * 2;

    auto load_chunk = [&](int c, int s) {
        const uint32_t stb = SB + (uint32_t)s * STAGEB;
        #pragma unroll
        for (int i = 0; i < 8; i++) {
            const int id = i * 256 + tid;
            const int t  = id >> 9;
            const int u  = id & 511;
            const int r  = u >> 2;
            const int c16 = u & 3;
            const char* base = (t == 0) ? baseA_h : (t == 1) ? baseA_l
                             : (t == 2) ? baseB_h : baseB_l;
            const char* src = base + (size_t)r * str + (size_t)c * 64 + (size_t)c16 * 16;
            const uint32_t dst = stb + (uint32_t)t * TILEB + (uint32_t)(r * ROWB + c16 * 16);
            CP16(dst, src);
        }
        CP_COMMIT();
    };

    float d[4][4][4];
    #pragma unroll
    for (int a = 0; a < 4; a++)
        #pragma unroll
        for (int b = 0; b < 4; b++)
            #pragma unroll
            for (int e = 0; e < 4; e++) d[a][b][e] = 0.0f;

    const int NC = EMB >> 5;
    load_chunk(0, 0);

    const uint32_t offA = (uint32_t)((wm * 64 + (lane & 7) + ((lane >> 3) & 1) * 8) * ROWB
                                     + ((lane >> 4) & 1) * 16);
    const uint32_t offB = (uint32_t)((wn * 32 + ((lane >> 4) & 1) * 8 + (lane & 7)) * ROWB
                                     + ((lane >> 3) & 1) * 16);

    for (int c = 0; c < NC; c++) {
        CP_WAIT0();
        __syncthreads();
        const int s = c & 1;
        if (c + 1 < NC) load_chunk(c + 1, s ^ 1);

        const uint32_t stb = SB + (uint32_t)s * STAGEB;
        const uint32_t Ah_s = stb,            Al_s = stb + TILEB;
        const uint32_t Bh_s = stb + 2*TILEB,  Bl_s = stb + 3*TILEB;

        #pragma unroll
        for (int kk = 0; kk < 2; kk++) {
            uint32_t bh[8], bl[8];
            ldsm4(&bh[0], Bh_s + offB + (uint32_t)(kk * 32));
            ldsm4(&bh[4], Bh_s + offB + (uint32_t)(16 * ROWB + kk * 32));
            ldsm4(&bl[0], Bl_s + offB + (uint32_t)(kk * 32));
            ldsm4(&bl[4], Bl_s + offB + (uint32_t)(16 * ROWB + kk * 32));
            #pragma unroll
            for (int mt = 0; mt < 4; mt++) {
                uint32_t ah[4], al[4];
                const uint32_t o = (uint32_t)(mt * 16 * ROWB) + (uint32_t)(kk * 32);
                ldsm4(ah, Ah_s + offA + o);
                ldsm4(al, Al_s + offA + o);
                #pragma unroll
                for (int nt = 0; nt < 4; nt++) {
                    mma16816(d[mt][nt], ah, &bh[nt * 2]);
                    mma16816(d[mt][nt], ah, &bl[nt * 2]);
                    mma16816(d[mt][nt], al, &bh[nt * 2]);
                }
            }
        }
    }
    __syncthreads();

    #pragma unroll
    for (int mt = 0; mt < 4; mt++) {
        #pragma unroll
        for (int nt = 0; nt < 4; nt++) {
            const int r0 = wm * 64 + mt * 16 + (lane >> 2);
            const int c0 = wn * 32 + nt * 8 + (lane & 3) * 2;
            #pragma unroll
            for (int h = 0; h < 2; h++) {
                float v0 = d[mt][nt][h * 2 + 0] + bias[bx * 128 + c0];
                float v1 = d[mt][nt][h * 2 + 1] + bias[bx * 128 + c0 + 1];
                *(float2*)&stg[(r0 + h * 8) * 132 + c0] = make_float2(v0, v1);
            }
        }
    }
    __syncthreads();

    const int row = tid >> 1, h = tid & 1;
    float* dst = outF + ((size_t)by * 128 + row) * EMB + (size_t)bx * 128 + h * 64;
    #pragma unroll
    for (int q = 0; q < 16; q++) {
        float4 v;
        v.x = stg[row * 132 + h * 64 + q * 4 + 0];
        v.y = stg[row * 132 + h * 64 + q * 4 + 1];
        v.z = stg[row * 132 + h * 64 + q * 4 + 2];
        v.w = stg[row * 132 + h * 64 + q * 4 + 3];
        ((float4*)dst)[q] = v;
    }
}

// ---------------------------------------------------------------------------
// fp32 -> bf16 hi/lo conversion: X, W_qkv, W_out in ONE launch
// ---------------------------------------------------------------------------
__global__ void conv_all(const float4* __restrict__ X,  __nv_bfloat16* __restrict__ Xh,  __nv_bfloat16* __restrict__ Xl,  int n1,
                         const float4* __restrict__ Wq, __nv_bfloat16* __restrict__ Wqh, __nv_bfloat16* __restrict__ Wql, int n2,
                         const float4* __restrict__ Wo, __nv_bfloat16* __restrict__ Woh, __nv_bfloat16* __restrict__ Wol, int n3)
{
    int i = blockIdx.x * 256 + threadIdx.x;
    const float4* src; __nv_bfloat16 *h, *l;
    if (i < n1)            { src = X;  h = Xh;  l = Xl;  }
    else if (i < n1 + n2)  { src = Wq; h = Wqh; l = Wql; i -= n1; }
    else if (i < n1+n2+n3) { src = Wo; h = Woh; l = Wol; i -= n1 + n2; }
    else return;
    const float4 v = src[i];
    const float vv[4] = {v.x, v.y, v.z, v.w};
    union { __nv_bfloat16 b[4]; uint2 u; } H, L;
    #pragma unroll
    for (int k = 0; k < 4; k++) {
        __nv_bfloat16 hi = __float2bfloat16(vv[k]);
        H.b[k] = hi;
        L.b[k] = __float2bfloat16(vv[k] - __bfloat162float(hi));
    }
    *(uint2*)(h + (size_t)i * 4) = H.u;
    *(uint2*)(l + (size_t)i * 4) = L.u;
}

// ---------------------------------------------------------------------------
// Masked softmax; emits att fp16 hi/lo. Vectorized.
// ---------------------------------------------------------------------------
__global__ void __launch_bounds__(256)
softmax_k(const float* __restrict__ att, const int* __restrict__ mask,
          __half* __restrict__ oh, __half* __restrict__ ol)
{
    const size_t row = blockIdx.x;
    const float4* a4 = (const float4*)(att  + row * (size_t)SLEN);
    const int4*   m4 = (const int4*)  (mask + row * (size_t)SLEN);
    const int tid = threadIdx.x;

    float v[8];
    const float4 x0 = a4[tid], x1 = a4[tid + 256];
    const int4   q0 = m4[tid], q1 = m4[tid + 256];
    v[0] = q0.x ? x0.x : -INFINITY;
    v[1] = q0.y ? x0.y : -INFINITY;
    v[2] = q0.z ? x0.z : -INFINITY;
    v[3] = q0.w ? x0.w : -INFINITY;
    v[4] = q1.x ? x1.x : -INFINITY;
    v[5] = q1.y ? x1.y : -INFINITY;
    v[6] = q1.z ? x1.z : -INFINITY;
    v[7] = q1.w ? x1.w : -INFINITY;

    float lmax = v[0];
    #pragma unroll
    for (int i = 1; i < 8; i++) lmax = fmaxf(lmax, v[i]);

    __shared__ float smax[8], ssum[8];
    #pragma unroll
    for (int o = 16; o > 0; o >>= 1)
        lmax = fmaxf(lmax, __shfl_xor_sync(0xffffffffu, lmax, o));
    if ((tid & 31) == 0) smax[tid >> 5] = lmax;
    __syncthreads();
    const float gmax = fmaxf(fmaxf(fmaxf(smax[0], smax[1]), fmaxf(smax[2], smax[3])),
                             fmaxf(fmaxf(smax[4], smax[5]), fmaxf(smax[6], smax[7])));
    float lsum = 0.0f;
    #pragma unroll
    for (int i = 0; i < 8; i++) { v[i] = __expf(v[i] - gmax); lsum += v[i]; }
    #pragma unroll
    for (int o = 16; o > 0; o >>= 1)
        lsum += __shfl_xor_sync(0xffffffffu, lsum, o);
    if ((tid & 31) == 0) ssum[tid >> 5] = lsum;
    __syncthreads();
    const float gsum = (ssum[0] + ssum[1]) + (ssum[2] + ssum[3])
                     + (ssum[4] + ssum[5]) + (ssum[6] + ssum[7]);
    const float inv = 1.0f / gsum;

    union { __half h[4]; uint2 u; } H0, L0, H1, L1;
    #pragma unroll
    for (int i = 0; i < 4; i++) {
        const float p = v[i] * inv;
        const __half hi = __float2half(p);
        H0.h[i] = hi;
        L0.h[i] = __float2half(p - __half2float(hi));
    }
    #pragma unroll
    for (int i = 0; i < 4; i++) {
        const float p = v[4 + i] * inv;
        const __half hi = __float2half(p);
        H1.h[i] = hi;
        L1.h[i] = __float2half(p - __half2float(hi));
    }
    const size_t base = row * (size_t)SLEN;
    *(uint2*)(oh + base + tid * 4)        = H0.u;
    *(uint2*)(ol + base + tid * 4)        = L0.u;
    *(uint2*)(oh + base + 1024 + tid * 4) = H1.u;
    *(uint2*)(ol + base + 1024 + tid * 4) = L1.u;
}

// ---------------------------------------------------------------------------
extern "C" void kernel_launch(void* const* d_in, const int* in_sizes, int n_in,
                              void* d_out, int out_size)
{
    const float* X     = (const float*)d_in[0];
    const int*   mask  = (const int*)  d_in[1];
    const float* W_qkv = (const float*)d_in[2];
    const float* b_qkv = (const float*)d_in[3];
    const float* W_out = (const float*)d_in[4];
    const float* b_out = (const float*)d_in[5];
    float*       out   = (float*)d_out;

    __nv_bfloat16 *Xh, *Xl, *Wqh, *Wql, *Woh, *Wol, *ch, *cl;
    __half *qf, *kfh, *kfl, *vtf, *athf, *atlf;
    float *att;
    cudaGetSymbolAddress((void**)&Xh,   g_Xh);   cudaGetSymbolAddress((void**)&Xl,   g_Xl);
    cudaGetSymbolAddress((void**)&Wqh,  g_Wqh);  cudaGetSymbolAddress((void**)&Wql,  g_Wql);
    cudaGetSymbolAddress((void**)&Woh,  g_Woh);  cudaGetSymbolAddress((void**)&Wol,  g_Wol);
    cudaGetSymbolAddress((void**)&qf,   g_qf);
    cudaGetSymbolAddress((void**)&kfh,  g_kfh);  cudaGetSymbolAddress((void**)&kfl,  g_kfl);
    cudaGetSymbolAddress((void**)&vtf,  g_vtf);
    cudaGetSymbolAddress((void**)&att,  g_att);
    cudaGetSymbolAddress((void**)&athf, g_athf); cudaGetSymbolAddress((void**)&atlf, g_atlf);
    cudaGetSymbolAddress((void**)&ch,   g_ch);   cudaGetSymbolAddress((void**)&cl,   g_cl);

    cudaFuncSetAttribute(gemm0_k,    cudaFuncAttributeMaxDynamicSharedMemorySize, GEMM_SMEM);
    cudaFuncSetAttribute(hgemm_k<1>, cudaFuncAttributeMaxDynamicSharedMemorySize, HG_SMEM);
    cudaFuncSetAttribute(hgemm_k<2>, cudaFuncAttributeMaxDynamicSharedMemorySize, HG_SMEM);
    cudaFuncSetAttribute(gemm3_k,    cudaFuncAttributeMaxDynamicSharedMemorySize, GEMM_SMEM);

    // Convert inputs to bf16 hi/lo (single launch)
    {
        const int n1 = BATCH*SLEN*EMB/4, n2 = QKVF*EMB/4, n3 = EMB*EMB/4;
        conv_all<<<(n1 + n2 + n3 + 255)/256, 256>>>(
            (const float4*)X, Xh, Xl, n1,
            (const float4*)W_qkv, Wqh, Wql, n2,
            (const float4*)W_out, Woh, Wol, n3);
    }

    // 1) qkv = X @ W_qkv^T + b  -> q fp16, k fp16 hi/lo, V^T fp16
    gemm0_k<<<dim3(QKVF/128, (BATCH*SLEN)/128), 256, GEMM_SMEM>>>(
        Xh, Xl, Wqh, Wql, b_qkv, qf, kfh, kfl, vtf);

    // 2) att = (Q @ K^T) / 32   (fp32, per batch) — q single, k split
    hgemm_k<1><<<dim3(SLEN/128, SLEN/128, BATCH), 256, HG_SMEM>>>(
        kfh, kfl, qf,
        (size_t)SLEN*EMB, EMB, (size_t)SLEN*EMB, EMB, EMB, 0.03125f,
        att, (size_t)SLEN*SLEN, SLEN, nullptr, nullptr);

    // 3) masked softmax -> att fp16 hi/lo
    softmax_k<<<BATCH*SLEN, 256>>>(att, mask, athf, atlf);

    // 4) ctx = att @ V  (B = V^T) — att split, V single -> ctx bf16 hi/lo
    hgemm_k<2><<<dim3(EMB/128, SLEN/128, BATCH), 256, HG_SMEM>>>(
        athf, atlf, vtf,
        (size_t)SLEN*SLEN, SLEN, (size_t)EMB*SLEN, SLEN, SLEN, 1.0f,
        nullptr, 0, 0, ch, cl);

    // 5) out = ctx @ W_out^T + b   (bf16x3)
    gemm3_k<<<dim3(EMB/128, (BATCH*SLEN)/128), 256, GEMM_SMEM>>>(
        ch, cl, Woh, Wol, out, b_out);
}

// round 11
// speedup vs baseline: 3.5287x; 1.2321x over previous
#include <cuda_runtime.h>
#include <cuda_bf16.h>
#include <cuda_fp16.h>
#include <math.h>
#include <stdint.h>

// Problem constants
#define BATCH 4
#define SLEN  2048
#define EMB   1024
#define QKVF  3072

// ---------------------------------------------------------------------------
// Device scratch (allocation-free rule: __device__ globals)
// ---------------------------------------------------------------------------
__device__ __align__(256) __half g_Xf [(size_t)BATCH*SLEN*EMB];   // X single fp16
__device__ __align__(256) __half g_Wqh[(size_t)QKVF*EMB];         // W_qkv fp16 hi
__device__ __align__(256) __half g_Wql[(size_t)QKVF*EMB];         // W_qkv fp16 lo
__device__ __align__(256) __half g_Wof[(size_t)EMB*EMB];          // W_out single fp16
__device__ __align__(256) __half g_qf [(size_t)BATCH*SLEN*EMB];   // q single fp16
__device__ __align__(256) __half g_kfh[(size_t)BATCH*SLEN*EMB];   // k fp16 hi
__device__ __align__(256) __half g_kfl[(size_t)BATCH*SLEN*EMB];   // k fp16 lo
__device__ __align__(256) __half g_vtf[(size_t)BATCH*EMB*SLEN];   // V^T single fp16
__device__ __align__(256) float  g_att[(size_t)BATCH*SLEN*SLEN];
__device__ __align__(256) __half g_athf[(size_t)BATCH*SLEN*SLEN]; // att fp16 hi
__device__ __align__(256) __half g_atlf[(size_t)BATCH*SLEN*SLEN]; // att fp16 lo
__device__ __align__(256) __half g_cfh[(size_t)BATCH*SLEN*EMB];   // ctx fp16 hi
__device__ __align__(256) __half g_cfl[(size_t)BATCH*SLEN*EMB];   // ctx fp16 lo

// ---------------------------------------------------------------------------
// PTX helpers (sm_80+ only — tcgen05 rejected by compute_103 PTX target)
// ---------------------------------------------------------------------------
__device__ __forceinline__ uint32_t smem_u32(const void* p) {
    uint32_t a;
    asm("{ .reg .u64 t; cvta.to.shared.u64 t, %1; cvt.u32.u64 %0, t; }"
        : "=r"(a) : "l"(p));
    return a;
}
#define CP16(d, s)   asm volatile("cp.async.cg.shared.global [%0], [%1], 16;" :: "r"(d), "l"(s))
#define CP_COMMIT()  asm volatile("cp.async.commit_group;" ::: "memory")
#define CP_WAIT0()   asm volatile("cp.async.wait_group 0;" ::: "memory")

__device__ __forceinline__ void ldsm4(uint32_t* r, uint32_t addr) {
    asm volatile("ldmatrix.sync.aligned.m8n8.x4.shared.b16 {%0,%1,%2,%3}, [%4];"
        : "=r"(r[0]), "=r"(r[1]), "=r"(r[2]), "=r"(r[3]) : "r"(addr));
}
__device__ __forceinline__ void hmma16816(float* d, const uint32_t* a, const uint32_t* b) {
    asm volatile("mma.sync.aligned.m16n8k16.row.col.f32.f16.f16.f32 "
        "{%0,%1,%2,%3}, {%4,%5,%6,%7}, {%8,%9}, {%0,%1,%2,%3};"
        : "+f"(d[0]), "+f"(d[1]), "+f"(d[2]), "+f"(d[3])
        : "r"(a[0]), "r"(a[1]), "r"(a[2]), "r"(a[3]), "r"(b[0]), "r"(b[1]));
}

// ---- fp16 2-MMA tiling: CTA 128x128, BK=64, 3 tiles/stage, 2 CTAs/SM ----
#define HROWB   144
#define HTILE   (128 * HROWB)
#define HSTAGE  (3 * HTILE)
#define HG_SMEM (2 * HSTAGE + 128)   // 110720 B

// ===========================================================================
// hgemm: fp16 one-side-exact (2 MMAs).  D[m,n] = alpha*sum_k A[m,k]B[n,k] (+bias)
// MODE 0 (qkv):    A = Sg (X single), B = S0/S1 (Wq hi/lo); bias;
//                  emit q fp16 / k fp16 hi-lo / V^T fp16 (transposed).
// MODE 1 (scores): A = Sg (q single), B = S0/S1 (k hi/lo); fp32 att out.
// MODE 2 (ctx):    A = S0/S1 (att hi/lo), B = Sg (V^T single); ctx fp16 hi/lo.
// MODE 3 (proj):   A = S0/S1 (ctx hi/lo), B = Sg (W_out single); bias; fp32 out.
// ===========================================================================
template<int MODE>
__global__ void __launch_bounds__(256, 2)
hgemm_k(const __half* __restrict__ S0, const __half* __restrict__ S1,
        const __half* __restrict__ Sg,
        size_t sS, int ldS, size_t sG, int ldG, int K, float alpha,
        float* __restrict__ outF, size_t sF, int ldF,
        __half* __restrict__ o0, __half* __restrict__ o1,
        __half* __restrict__ o2, __half* __restrict__ o3,
        const float* __restrict__ bias)
{
    extern __shared__ char dsm[];
    const uint32_t sb0 = smem_u32(dsm);
    const uint32_t SB  = (sb0 + 127u) & ~127u;
    float* stg = (float*)(dsm + (SB - sb0));

    const int tid  = threadIdx.x;
    const int wid  = tid >> 5, lane = tid & 31;
    const int wm   = wid >> 2, wn = wid & 3;    // warp 64x32
    const int bx = blockIdx.x, by = blockIdx.y, z = blockIdx.z;

    constexpr bool SPLIT_A = (MODE >= 2);
    const int splitRow  = (SPLIT_A ? by : bx) * 128;
    const int singleRow = (SPLIT_A ? bx : by) * 128;
    const char* b0 = (const char*)(S0 + (size_t)z * sS + (size_t)splitRow * ldS);
    const char* b1 = (const char*)(S1 + (size_t)z * sS + (size_t)splitRow * ldS);
    const char* bg = (const char*)(Sg + (size_t)z * sG + (size_t)singleRow * ldG);
    const size_t strS = (size_t)ldS * 2, strG = (size_t)ldG * 2;

    auto load_chunk = [&](int c, int s) {
        const uint32_t stb = SB + (uint32_t)s * HSTAGE;
        #pragma unroll
        for (int i = 0; i < 12; i++) {
            const int id = i * 256 + tid;       // 0..3071
            const int t  = id >> 10;            // tile 0..2
            const int u  = id & 1023;
            const int r  = u >> 3;              // row 0..127
            const int c16 = u & 7;              // 16B piece 0..7
            const char* base = (t == 0) ? b0 : (t == 1) ? b1 : bg;
            const size_t str = (t < 2) ? strS : strG;
            const char* src = base + (size_t)r * str + (size_t)c * 128 + (size_t)c16 * 16;
            const uint32_t dst = stb + (uint32_t)t * HTILE + (uint32_t)(r * HROWB + c16 * 16);
            CP16(dst, src);
        }
        CP_COMMIT();
    };

    float d[4][4][4];
    #pragma unroll
    for (int a = 0; a < 4; a++)
        #pragma unroll
        for (int b = 0; b < 4; b++)
            #pragma unroll
            for (int e = 0; e < 4; e++) d[a][b][e] = 0.0f;

    const int NC = K >> 6;
    load_chunk(0, 0);

    const uint32_t offA = (uint32_t)((wm * 64 + (lane & 7) + ((lane >> 3) & 1) * 8) * HROWB
                                     + ((lane >> 4) & 1) * 16);
    const uint32_t offB = (uint32_t)((wn * 32 + ((lane >> 4) & 1) * 8 + (lane & 7)) * HROWB
                                     + ((lane >> 3) & 1) * 16);

    for (int c = 0; c < NC; c++) {
        CP_WAIT0();
        __syncthreads();
        const int s = c & 1;
        if (c + 1 < NC) load_chunk(c + 1, s ^ 1);

        const uint32_t stb = SB + (uint32_t)s * HSTAGE;

        if (!SPLIT_A) {      // split B (hi/lo), single A
            const uint32_t Bh_s = stb, Bl_s = stb + HTILE, A_s = stb + 2 * HTILE;
            #pragma unroll
            for (int kk = 0; kk < 4; kk++) {
                uint32_t p0[8], p1[8];
                ldsm4(&p0[0], Bh_s + offB + (uint32_t)(kk * 32));
                ldsm4(&p0[4], Bh_s + offB + (uint32_t)(16 * HROWB + kk * 32));
                ldsm4(&p1[0], Bl_s + offB + (uint32_t)(kk * 32));
                ldsm4(&p1[4], Bl_s + offB + (uint32_t)(16 * HROWB + kk * 32));
                #pragma unroll
                for (int mt = 0; mt < 4; mt++) {
                    uint32_t a[4];
                    ldsm4(a, A_s + offA + (uint32_t)(mt * 16 * HROWB + kk * 32));
                    #pragma unroll
                    for (int nt = 0; nt < 4; nt++) {
                        hmma16816(d[mt][nt], a, &p0[nt * 2]);
                        hmma16816(d[mt][nt], a, &p1[nt * 2]);
                    }
                }
            }
        } else {             // split A (hi/lo), single B
            const uint32_t Ah_s = stb, Al_s = stb + HTILE, B_s = stb + 2 * HTILE;
            #pragma unroll
            for (int kk = 0; kk < 4; kk++) {
                uint32_t bq[8];
                ldsm4(&bq[0], B_s + offB + (uint32_t)(kk * 32));
                ldsm4(&bq[4], B_s + offB + (uint32_t)(16 * HROWB + kk * 32));
                #pragma unroll
                for (int mt = 0; mt < 4; mt++) {
                    uint32_t ah[4], al[4];
                    const uint32_t o = (uint32_t)(mt * 16 * HROWB + kk * 32);
                    ldsm4(ah, Ah_s + offA + o);
                    ldsm4(al, Al_s + offA + o);
                    #pragma unroll
                    for (int nt = 0; nt < 4; nt++) {
                        hmma16816(d[mt][nt], ah, &bq[nt * 2]);
                        hmma16816(d[mt][nt], al, &bq[nt * 2]);
                    }
                }
            }
        }
    }
    __syncthreads();

    // ---- accumulators -> smem staging (alpha, optional bias) ----
    #pragma unroll
    for (int mt = 0; mt < 4; mt++) {
        #pragma unroll
        for (int nt = 0; nt < 4; nt++) {
            const int r0 = wm * 64 + mt * 16 + (lane >> 2);
            const int c0 = wn * 32 + nt * 8 + (lane & 3) * 2;
            #pragma unroll
            for (int h = 0; h < 2; h++) {
                float v0 = d[mt][nt][h * 2 + 0] * alpha;
                float v1 = d[mt][nt][h * 2 + 1] * alpha;
                if (MODE == 0 || MODE == 3) {
                    v0 += bias[bx * 128 + c0];
                    v1 += bias[bx * 128 + c0 + 1];
                }
                *(float2*)&stg[(r0 + h * 8) * 132 + c0] = make_float2(v0, v1);
            }
        }
    }
    __syncthreads();

    // ---- MODE-specific writers ----
    if (MODE == 1 || MODE == 3) {
        const int row = tid >> 1, h = tid & 1;
        float* dst = outF + (size_t)z * sF + ((size_t)by * 128 + row) * ldF
                   + (size_t)bx * 128 + h * 64;
        #pragma unroll
        for (int q = 0; q < 16; q++) {
            float4 v;
            v.x = stg[row * 132 + h * 64 + q * 4 + 0];
            v.y = stg[row * 132 + h * 64 + q * 4 + 1];
            v.z = stg[row * 132 + h * 64 + q * 4 + 2];
            v.w = stg[row * 132 + h * 64 + q * 4 + 3];
            ((float4*)dst)[q] = v;
        }
    } else if (MODE == 2) {
        // ctx -> fp16 hi/lo (row-major): o0 = hi, o1 = lo
        #pragma unroll 1
        for (int cb = 0; cb < 4; cb++) {
            #pragma unroll 1
            for (int it = 0; it < 2; it++) {
                const int row = it * 64 + (tid >> 2);
                const int qq  = tid & 3;
                const int col = cb * 32 + qq * 8;
                const size_t rg = (size_t)z * SLEN + (size_t)by * 128 + row;
                union { __half h[8]; uint4 v; } Uh, Ul;
                #pragma unroll
                for (int i = 0; i < 8; i++) {
                    float v = stg[row * 132 + col + i];
                    __half hi = __float2half(v);
                    Uh.h[i] = hi;
                    Ul.h[i] = __float2half(v - __half2float(hi));
                }
                const size_t off = rg * 1024 + bx * 128 + col;
                *(uint4*)(o0 + off) = Uh.v;
                *(uint4*)(o1 + off) = Ul.v;
            }
        }
    } else if (MODE == 0 && bx < 8) {       // q -> single fp16 (o0)
        #pragma unroll 1
        for (int cb = 0; cb < 4; cb++) {
            #pragma unroll 1
            for (int it = 0; it < 2; it++) {
                const int row = it * 64 + (tid >> 2);
                const int qq  = tid & 3;
                const int col = cb * 32 + qq * 8;
                const size_t rg = (size_t)by * 128 + row;
                union { __half h[8]; uint4 v; } U;
                #pragma unroll
                for (int i = 0; i < 8; i++)
                    U.h[i] = __float2half(stg[row * 132 + col + i]);
                *(uint4*)(o0 + rg * 1024 + bx * 128 + col) = U.v;
            }
        }
    } else if (MODE == 0 && bx < 16) {      // k -> fp16 hi/lo (o1, o2)
        #pragma unroll 1
        for (int cb = 0; cb < 4; cb++) {
            #pragma unroll 1
            for (int it = 0; it < 2; it++) {
                const int row = it * 64 + (tid >> 2);
                const int qq  = tid & 3;
                const int col = cb * 32 + qq * 8;
                const size_t rg = (size_t)by * 128 + row;
                union { __half h[8]; uint4 v; } Uh, Ul;
                #pragma unroll
                for (int i = 0; i < 8; i++) {
                    float v = stg[row * 132 + col + i];
                    __half hi = __float2half(v);
                    Uh.h[i] = hi;
                    Ul.h[i] = __float2half(v - __half2float(hi));
                }
                const size_t off = rg * 1024 + (bx - 8) * 128 + col;
                *(uint4*)(o1 + off) = Uh.v;
                *(uint4*)(o2 + off) = Ul.v;
            }
        }
    } else if (MODE == 0) {                 // V^T single fp16, transposed (o3)
        const int j  = tid >> 3;
        const int rs = tid & 7;
        const int bidx = by >> 4;
        const int s0 = (by * 128) & 2047;
        #pragma unroll 1
        for (int cb = 0; cb < 4; cb++) {
            const int col = cb * 32 + j;
            const int colE = (bx - 16) * 128 + col;
            union { __half h[16]; uint4 v[2]; } U;
            #pragma unroll
            for (int i = 0; i < 16; i++)
                U.h[i] = __float2half(stg[(rs * 16 + i) * 132 + col]);
            const size_t off = ((size_t)bidx * 1024 + colE) * 2048 + s0 + rs * 16;
            *(uint4*)(o3 + off)     = U.v[0];
            *(uint4*)(o3 + off + 8) = U.v[1];
        }
    }
}

// ---------------------------------------------------------------------------
// Input conversion: X -> fp16 single, W_qkv -> fp16 hi/lo, W_out -> fp16 single
// ---------------------------------------------------------------------------
__global__ void conv_all(const float4* __restrict__ X,  __half* __restrict__ Xf, int n1,
                         const float4* __restrict__ Wq, __half* __restrict__ Wqh,
                         __half* __restrict__ Wql, int n2,
                         const float4* __restrict__ Wo, __half* __restrict__ Wof, int n3)
{
    int i = blockIdx.x * 256 + threadIdx.x;
    if (i < n1) {
        const float4 v = X[i];
        union { __half h[4]; uint2 u; } U;
        U.h[0] = __float2half(v.x); U.h[1] = __float2half(v.y);
        U.h[2] = __float2half(v.z); U.h[3] = __float2half(v.w);
        *(uint2*)(Xf + (size_t)i * 4) = U.u;
    } else if (i < n1 + n2) {
        i -= n1;
        const float4 v = Wq[i];
        const float vv[4] = {v.x, v.y, v.z, v.w};
        union { __half h[4]; uint2 u; } H, L;
        #pragma unroll
        for (int k = 0; k < 4; k++) {
            __half hi = __float2half(vv[k]);
            H.h[k] = hi;
            L.h[k] = __float2half(vv[k] - __half2float(hi));
        }
        *(uint2*)(Wqh + (size_t)i * 4) = H.u;
        *(uint2*)(Wql + (size_t)i * 4) = L.u;
    } else if (i < n1 + n2 + n3) {
        i -= n1 + n2;
        const float4 v = Wo[i];
        union { __half h[4]; uint2 u; } U;
        U.h[0] = __float2half(v.x); U.h[1] = __float2half(v.y);
        U.h[2] = __float2half(v.z); U.h[3] = __float2half(v.w);
        *(uint2*)(Wof + (size_t)i * 4) = U.u;
    }
}

// ---------------------------------------------------------------------------
// Masked softmax; emits att fp16 hi/lo. Vectorized.
// ---------------------------------------------------------------------------
__global__ void __launch_bounds__(256)
softmax_k(const float* __restrict__ att, const int* __restrict__ mask,
          __half* __restrict__ oh, __half* __restrict__ ol)
{
    const size_t row = blockIdx.x;
    const float4* a4 = (const float4*)(att  + row * (size_t)SLEN);
    const int4*   m4 = (const int4*)  (mask + row * (size_t)SLEN);
    const int tid = threadIdx.x;

    float v[8];
    const float4 x0 = a4[tid], x1 = a4[tid + 256];
    const int4   q0 = m4[tid], q1 = m4[tid + 256];
    v[0] = q0.x ? x0.x : -INFINITY;
    v[1] = q0.y ? x0.y : -INFINITY;
    v[2] = q0.z ? x0.z : -INFINITY;
    v[3] = q0.w ? x0.w : -INFINITY;
    v[4] = q1.x ? x1.x : -INFINITY;
    v[5] = q1.y ? x1.y : -INFINITY;
    v[6] = q1.z ? x1.z : -INFINITY;
    v[7] = q1.w ? x1.w : -INFINITY;

    float lmax = v[0];
    #pragma unroll
    for (int i = 1; i < 8; i++) lmax = fmaxf(lmax, v[i]);

    __shared__ float smax[8], ssum[8];
    #pragma unroll
    for (int o = 16; o > 0; o >>= 1)
        lmax = fmaxf(lmax, __shfl_xor_sync(0xffffffffu, lmax, o));
    if ((tid & 31) == 0) smax[tid >> 5] = lmax;
    __syncthreads();
    const float gmax = fmaxf(fmaxf(fmaxf(smax[0], smax[1]), fmaxf(smax[2], smax[3])),
                             fmaxf(fmaxf(smax[4], smax[5]), fmaxf(smax[6], smax[7])));
    float lsum = 0.0f;
    #pragma unroll
    for (int i = 0; i < 8; i++) { v[i] = __expf(v[i] - gmax); lsum += v[i]; }
    #pragma unroll
    for (int o = 16; o > 0; o >>= 1)
        lsum += __shfl_xor_sync(0xffffffffu, lsum, o);
    if ((tid & 31) == 0) ssum[tid >> 5] = lsum;
    __syncthreads();
    const float gsum = (ssum[0] + ssum[1]) + (ssum[2] + ssum[3])
                     + (ssum[4] + ssum[5]) + (ssum[6] + ssum[7]);
    const float inv = 1.0f / gsum;

    union { __half h[4]; uint2 u; } H0, L0, H1, L1;
    #pragma unroll
    for (int i = 0; i < 4; i++) {
        const float p = v[i] * inv;
        const __half hi = __float2half(p);
        H0.h[i] = hi;
        L0.h[i] = __float2half(p - __half2float(hi));
    }
    #pragma unroll
    for (int i = 0; i < 4; i++) {
        const float p = v[4 + i] * inv;
        const __half hi = __float2half(p);
        H1.h[i] = hi;
        L1.h[i] = __float2half(p - __half2float(hi));
    }
    const size_t base = row * (size_t)SLEN;
    *(uint2*)(oh + base + tid * 4)        = H0.u;
    *(uint2*)(ol + base + tid * 4)        = L0.u;
    *(uint2*)(oh + base + 1024 + tid * 4) = H1.u;
    *(uint2*)(ol + base + 1024 + tid * 4) = L1.u;
}

// ---------------------------------------------------------------------------
extern "C" void kernel_launch(void* const* d_in, const int* in_sizes, int n_in,
                              void* d_out, int out_size)
{
    const float* X     = (const float*)d_in[0];
    const int*   mask  = (const int*)  d_in[1];
    const float* W_qkv = (const float*)d_in[2];
    const float* b_qkv = (const float*)d_in[3];
    const float* W_out = (const float*)d_in[4];
    const float* b_out = (const float*)d_in[5];
    float*       out   = (float*)d_out;

    __half *Xf, *Wqh, *Wql, *Wof, *qf, *kfh, *kfl, *vtf, *athf, *atlf, *cfh, *cfl;
    float *att;
    cudaGetSymbolAddress((void**)&Xf,   g_Xf);
    cudaGetSymbolAddress((void**)&Wqh,  g_Wqh);  cudaGetSymbolAddress((void**)&Wql,  g_Wql);
    cudaGetSymbolAddress((void**)&Wof,  g_Wof);
    cudaGetSymbolAddress((void**)&qf,   g_qf);
    cudaGetSymbolAddress((void**)&kfh,  g_kfh);  cudaGetSymbolAddress((void**)&kfl,  g_kfl);
    cudaGetSymbolAddress((void**)&vtf,  g_vtf);
    cudaGetSymbolAddress((void**)&att,  g_att);
    cudaGetSymbolAddress((void**)&athf, g_athf); cudaGetSymbolAddress((void**)&atlf, g_atlf);
    cudaGetSymbolAddress((void**)&cfh,  g_cfh);  cudaGetSymbolAddress((void**)&cfl,  g_cfl);

    cudaFuncSetAttribute(hgemm_k<0>, cudaFuncAttributeMaxDynamicSharedMemorySize, HG_SMEM);
    cudaFuncSetAttribute(hgemm_k<1>, cudaFuncAttributeMaxDynamicSharedMemorySize, HG_SMEM);
    cudaFuncSetAttribute(hgemm_k<2>, cudaFuncAttributeMaxDynamicSharedMemorySize, HG_SMEM);
    cudaFuncSetAttribute(hgemm_k<3>, cudaFuncAttributeMaxDynamicSharedMemorySize, HG_SMEM);

    // Convert inputs (single launch)
    {
        const int n1 = BATCH*SLEN*EMB/4, n2 = QKVF*EMB/4, n3 = EMB*EMB/4;
        conv_all<<<(n1 + n2 + n3 + 255)/256, 256>>>(
            (const float4*)X, Xf, n1,
            (const float4*)W_qkv, Wqh, Wql, n2,
            (const float4*)W_out, Wof, n3);
    }

    // 1) qkv = X @ W_qkv^T + b — X single, Wq split -> q fp16, k hi/lo, V^T fp16
    hgemm_k<0><<<dim3(QKVF/128, (BATCH*SLEN)/128), 256, HG_SMEM>>>(
        Wqh, Wql, Xf,
        0, EMB, 0, EMB, EMB, 1.0f,
        nullptr, 0, 0, qf, kfh, kfl, vtf, b_qkv);

    // 2) att = (Q @ K^T) / 32 — q single, k split (fp32 out, per batch)
    hgemm_k<1><<<dim3(SLEN/128, SLEN/128, BATCH), 256, HG_SMEM>>>(
        kfh, kfl, qf,
        (size_t)SLEN*EMB, EMB, (size_t)SLEN*EMB, EMB, EMB, 0.03125f,
        att, (size_t)SLEN*SLEN, SLEN, nullptr, nullptr, nullptr, nullptr, nullptr);

    // 3) masked softmax -> att fp16 hi/lo
    softmax_k<<<BATCH*SLEN, 256>>>(att, mask, athf, atlf);

    // 4) ctx = att @ V — att split, V single -> ctx fp16 hi/lo
    hgemm_k<2><<<dim3(EMB/128, SLEN/128, BATCH), 256, HG_SMEM>>>(
        athf, atlf, vtf,
        (size_t)SLEN*SLEN, SLEN, (size_t)EMB*SLEN, SLEN, SLEN, 1.0f,
        nullptr, 0, 0, cfh, cfl, nullptr, nullptr, nullptr);

    // 5) out = ctx @ W_out^T + b — ctx split, W_out single (fp32 out)
    hgemm_k<3><<<dim3(EMB/128, (BATCH*SLEN)/128), 256, HG_SMEM>>>(
        cfh, cfl, Wof,
        0, EMB, 0, EMB, EMB, 1.0f,
        out, 0, EMB, nullptr, nullptr, nullptr, nullptr, b_out);
}

// round 12
// speedup vs baseline: 4.4348x; 1.2568x over previous
#include <cuda_runtime.h>
#include <cuda_bf16.h>
#include <cuda_fp16.h>
#include <math.h>
#include <stdint.h>

// Problem constants
#define BATCH 4
#define SLEN  2048
#define EMB   1024
#define QKVF  3072

// ---------------------------------------------------------------------------
// Device scratch (allocation-free rule: __device__ globals)
// ---------------------------------------------------------------------------
__device__ __align__(256) __half g_Xf [(size_t)BATCH*SLEN*EMB];   // X single fp16
__device__ __align__(256) __half g_Wqh[(size_t)QKVF*EMB];         // W_qkv fp16 hi
__device__ __align__(256) __half g_Wql[(size_t)QKVF*EMB];         // W_qkv fp16 lo
__device__ __align__(256) __half g_Wof[(size_t)EMB*EMB];          // W_out single fp16
__device__ __align__(256) __half g_qf [(size_t)BATCH*SLEN*EMB];   // q single fp16
__device__ __align__(256) __half g_kf [(size_t)BATCH*SLEN*EMB];   // k single fp16
__device__ __align__(256) __half g_vtf[(size_t)BATCH*EMB*SLEN];   // V^T single fp16
__device__ __align__(256) float  g_att[(size_t)BATCH*SLEN*SLEN];
__device__ __align__(256) __half g_athf[(size_t)BATCH*SLEN*SLEN]; // att single fp16
__device__ __align__(256) __half g_cfh[(size_t)BATCH*SLEN*EMB];   // ctx fp16 hi
__device__ __align__(256) __half g_cfl[(size_t)BATCH*SLEN*EMB];   // ctx fp16 lo

// ---------------------------------------------------------------------------
// PTX helpers (sm_80+ only — tcgen05 rejected by compute_103 PTX target)
// ---------------------------------------------------------------------------
__device__ __forceinline__ uint32_t smem_u32(const void* p) {
    uint32_t a;
    asm("{ .reg .u64 t; cvta.to.shared.u64 t, %1; cvt.u32.u64 %0, t; }"
        : "=r"(a) : "l"(p));
    return a;
}
#define CP16(d, s)   asm volatile("cp.async.cg.shared.global [%0], [%1], 16;" :: "r"(d), "l"(s))
#define CP_COMMIT()  asm volatile("cp.async.commit_group;" ::: "memory")
#define CP_WAIT0()   asm volatile("cp.async.wait_group 0;" ::: "memory")

__device__ __forceinline__ void ldsm4(uint32_t* r, uint32_t addr) {
    asm volatile("ldmatrix.sync.aligned.m8n8.x4.shared.b16 {%0,%1,%2,%3}, [%4];"
        : "=r"(r[0]), "=r"(r[1]), "=r"(r[2]), "=r"(r[3]) : "r"(addr));
}
__device__ __forceinline__ void hmma16816(float* d, const uint32_t* a, const uint32_t* b) {
    asm volatile("mma.sync.aligned.m16n8k16.row.col.f32.f16.f16.f32 "
        "{%0,%1,%2,%3}, {%4,%5,%6,%7}, {%8,%9}, {%0,%1,%2,%3};"
        : "+f"(d[0]), "+f"(d[1]), "+f"(d[2]), "+f"(d[3])
        : "r"(a[0]), "r"(a[1]), "r"(a[2]), "r"(a[3]), "r"(b[0]), "r"(b[1]));
}

// ---- fp16 tiling: CTA 128x128, BK=64, 8 warps (2x4), 2 CTAs/SM ----
#define HROWB   144
#define HTILE   (128 * HROWB)        // 18432 B
#define HG_SMEM3 (2 * 3 * HTILE + 128)   // split modes: 110720 B
#define HG_SMEM2 (2 * 2 * HTILE + 128)   // pure  modes:  73856 B

// ===========================================================================
// hgemm:  D[m,n] = alpha*sum_k A[m,k]B[n,k] (+bias)
// MODE 0 (qkv, 2-MMA):   A = Sg (X single), B = S0/S1 (Wq hi/lo); bias;
//                        emit q fp16 / k fp16 / V^T fp16 (transposed).
// MODE 1 (scores, pure): A = Sg (q), B = S0 (k); fp32 att out.
// MODE 2 (ctx, pure):    A = Sg (att), B = S0 (V^T); ctx fp16 hi/lo out.
// MODE 3 (proj, 2-MMA):  A = S0/S1 (ctx hi/lo), B = Sg (W_out); bias; fp32 out.
// ===========================================================================
template<int MODE>
__global__ void __launch_bounds__(256, 2)
hgemm_k(const __half* __restrict__ S0, const __half* __restrict__ S1,
        const __half* __restrict__ Sg,
        size_t sS, int ldS, size_t sG, int ldG, int K, float alpha,
        float* __restrict__ outF, size_t sF, int ldF,
        __half* __restrict__ o0, __half* __restrict__ o1,
        __half* __restrict__ o3,
        const float* __restrict__ bias)
{
    extern __shared__ char dsm[];
    const uint32_t sb0 = smem_u32(dsm);
    const uint32_t SB  = (sb0 + 127u) & ~127u;
    float* stg = (float*)(dsm + (SB - sb0));

    const int tid  = threadIdx.x;
    const int wid  = tid >> 5, lane = tid & 31;
    const int wm   = wid >> 2, wn = wid & 3;    // warp 64x32
    const int bx = blockIdx.x, by = blockIdx.y, z = blockIdx.z;

    constexpr bool PURE    = (MODE == 1 || MODE == 2);
    constexpr bool SPLIT_A = (MODE == 3);
    constexpr int  NTILES  = PURE ? 2 : 3;
    constexpr uint32_t HSTAGE = (uint32_t)NTILES * HTILE;

    const int splitRow  = (SPLIT_A ? by : bx) * 128;   // rows of S0/S1
    const int singleRow = (SPLIT_A ? bx : by) * 128;   // rows of Sg
    const char* b0 = (const char*)(S0 + (size_t)z * sS + (size_t)splitRow * ldS);
    const char* b1 = PURE ? nullptr
                   : (const char*)(S1 + (size_t)z * sS + (size_t)splitRow * ldS);
    const char* bg = (const char*)(Sg + (size_t)z * sG + (size_t)singleRow * ldG);
    const size_t strS = (size_t)ldS * 2, strG = (size_t)ldG * 2;

    auto load_chunk = [&](int c, int s) {
        const uint32_t stb = SB + (uint32_t)s * HSTAGE;
        #pragma unroll
        for (int i = 0; i < NTILES * 4; i++) {
            const int id = i * 256 + tid;
            const int t  = id >> 10;            // tile 0..NTILES-1
            const int u  = id & 1023;
            const int r  = u >> 3;
            const int c16 = u & 7;
            const char* base; size_t str;
            if (t == 0)              { base = b0; str = strS; }
            else if (PURE || t == 2) { base = bg; str = strG; }
            else                     { base = b1; str = strS; }
            const char* src = base + (size_t)r * str + (size_t)c * 128 + (size_t)c16 * 16;
            const uint32_t dst = stb + (uint32_t)t * HTILE + (uint32_t)(r * HROWB + c16 * 16);
            CP16(dst, src);
        }
        CP_COMMIT();
    };

    float d[4][4][4];
    #pragma unroll
    for (int a = 0; a < 4; a++)
        #pragma unroll
        for (int b = 0; b < 4; b++)
            #pragma unroll
            for (int e = 0; e < 4; e++) d[a][b][e] = 0.0f;

    const int NC = K >> 6;
    load_chunk(0, 0);

    const uint32_t offA = (uint32_t)((wm * 64 + (lane & 7) + ((lane >> 3) & 1) * 8) * HROWB
                                     + ((lane >> 4) & 1) * 16);
    const uint32_t offB = (uint32_t)((wn * 32 + ((lane >> 4) & 1) * 8 + (lane & 7)) * HROWB
                                     + ((lane >> 3) & 1) * 16);

    for (int c = 0; c < NC; c++) {
        CP_WAIT0();
        __syncthreads();
        const int s = c & 1;
        if (c + 1 < NC) load_chunk(c + 1, s ^ 1);

        const uint32_t stb = SB + (uint32_t)s * HSTAGE;

        if (PURE) {          // single x single, 1 MMA
            const uint32_t B_s = stb, A_s = stb + HTILE;
            #pragma unroll
            for (int kk = 0; kk < 4; kk++) {
                uint32_t bq[8];
                ldsm4(&bq[0], B_s + offB + (uint32_t)(kk * 32));
                ldsm4(&bq[4], B_s + offB + (uint32_t)(16 * HROWB + kk * 32));
                #pragma unroll
                for (int mt = 0; mt < 4; mt++) {
                    uint32_t a[4];
                    ldsm4(a, A_s + offA + (uint32_t)(mt * 16 * HROWB + kk * 32));
                    #pragma unroll
                    for (int nt = 0; nt < 4; nt++)
                        hmma16816(d[mt][nt], a, &bq[nt * 2]);
                }
            }
        } else if (!SPLIT_A) {   // split B (hi/lo), single A — 2 MMAs
            const uint32_t Bh_s = stb, Bl_s = stb + HTILE, A_s = stb + 2 * HTILE;
            #pragma unroll
            for (int kk = 0; kk < 4; kk++) {
                uint32_t p0[8], p1[8];
                ldsm4(&p0[0], Bh_s + offB + (uint32_t)(kk * 32));
                ldsm4(&p0[4], Bh_s + offB + (uint32_t)(16 * HROWB + kk * 32));
                ldsm4(&p1[0], Bl_s + offB + (uint32_t)(kk * 32));
                ldsm4(&p1[4], Bl_s + offB + (uint32_t)(16 * HROWB + kk * 32));
                #pragma unroll
                for (int mt = 0; mt < 4; mt++) {
                    uint32_t a[4];
                    ldsm4(a, A_s + offA + (uint32_t)(mt * 16 * HROWB + kk * 32));
                    #pragma unroll
                    for (int nt = 0; nt < 4; nt++) {
                        hmma16816(d[mt][nt], a, &p0[nt * 2]);
                        hmma16816(d[mt][nt], a, &p1[nt * 2]);
                    }
                }
            }
        } else {             // split A (hi/lo), single B — 2 MMAs
            const uint32_t Ah_s = stb, Al_s = stb + HTILE, B_s = stb + 2 * HTILE;
            #pragma unroll
            for (int kk = 0; kk < 4; kk++) {
                uint32_t bq[8];
                ldsm4(&bq[0], B_s + offB + (uint32_t)(kk * 32));
                ldsm4(&bq[4], B_s + offB + (uint32_t)(16 * HROWB + kk * 32));
                #pragma unroll
                for (int mt = 0; mt < 4; mt++) {
                    uint32_t ah[4], al[4];
                    const uint32_t o = (uint32_t)(mt * 16 * HROWB + kk * 32);
                    ldsm4(ah, Ah_s + offA + o);
                    ldsm4(al, Al_s + offA + o);
                    #pragma unroll
                    for (int nt = 0; nt < 4; nt++) {
                        hmma16816(d[mt][nt], ah, &bq[nt * 2]);
                        hmma16816(d[mt][nt], al, &bq[nt * 2]);
                    }
                }
            }
        }
    }
    __syncthreads();

    // ---- accumulators -> smem staging (alpha, optional bias) ----
    #pragma unroll
    for (int mt = 0; mt < 4; mt++) {
        #pragma unroll
        for (int nt = 0; nt < 4; nt++) {
            const int r0 = wm * 64 + mt * 16 + (lane >> 2);
            const int c0 = wn * 32 + nt * 8 + (lane & 3) * 2;
            #pragma unroll
            for (int h = 0; h < 2; h++) {
                float v0 = d[mt][nt][h * 2 + 0] * alpha;
                float v1 = d[mt][nt][h * 2 + 1] * alpha;
                if (MODE == 0 || MODE == 3) {
                    v0 += bias[bx * 128 + c0];
                    v1 += bias[bx * 128 + c0 + 1];
                }
                *(float2*)&stg[(r0 + h * 8) * 132 + c0] = make_float2(v0, v1);
            }
        }
    }
    __syncthreads();

    // ---- MODE-specific writers ----
    if (MODE == 1 || MODE == 3) {
        const int row = tid >> 1, h = tid & 1;
        float* dst = outF + (size_t)z * sF + ((size_t)by * 128 + row) * ldF
                   + (size_t)bx * 128 + h * 64;
        #pragma unroll
        for (int q = 0; q < 16; q++) {
            float4 v;
            v.x = stg[row * 132 + h * 64 + q * 4 + 0];
            v.y = stg[row * 132 + h * 64 + q * 4 + 1];
            v.z = stg[row * 132 + h * 64 + q * 4 + 2];
            v.w = stg[row * 132 + h * 64 + q * 4 + 3];
            ((float4*)dst)[q] = v;
        }
    } else if (MODE == 2) {
        // ctx -> fp16 hi/lo (row-major): o0 = hi, o1 = lo
        #pragma unroll 1
        for (int cb = 0; cb < 4; cb++) {
            #pragma unroll 1
            for (int it = 0; it < 2; it++) {
                const int row = it * 64 + (tid >> 2);
                const int qq  = tid & 3;
                const int col = cb * 32 + qq * 8;
                const size_t rg = (size_t)z * SLEN + (size_t)by * 128 + row;
                union { __half h[8]; uint4 v; } Uh, Ul;
                #pragma unroll
                for (int i = 0; i < 8; i++) {
                    float v = stg[row * 132 + col + i];
                    __half hi = __float2half(v);
                    Uh.h[i] = hi;
                    Ul.h[i] = __float2half(v - __half2float(hi));
                }
                const size_t off = rg * 1024 + bx * 128 + col;
                *(uint4*)(o0 + off) = Uh.v;
                *(uint4*)(o1 + off) = Ul.v;
            }
        }
    } else if (MODE == 0 && bx < 16) {      // q (bx<8 -> o0) or k (bx<16 -> o1), single fp16
        __half* O = (bx < 8) ? o0 : o1;
        const int cbase = (bx & 7) * 128;
        #pragma unroll 1
        for (int cb = 0; cb < 4; cb++) {
            #pragma unroll 1
            for (int it = 0; it < 2; it++) {
                const int row = it * 64 + (tid >> 2);
                const int qq  = tid & 3;
                const int col = cb * 32 + qq * 8;
                const size_t rg = (size_t)by * 128 + row;
                union { __half h[8]; uint4 v; } U;
                #pragma unroll
                for (int i = 0; i < 8; i++)
                    U.h[i] = __float2half(stg[row * 132 + col + i]);
                *(uint4*)(O + rg * 1024 + cbase + col) = U.v;
            }
        }
    } else if (MODE == 0) {                 // V^T single fp16, transposed (o3)
        const int j  = tid >> 3;
        const int rs = tid & 7;
        const int bidx = by >> 4;
        const int s0 = (by * 128) & 2047;
        #pragma unroll 1
        for (int cb = 0; cb < 4; cb++) {
            const int col = cb * 32 + j;
            const int colE = (bx - 16) * 128 + col;
            union { __half h[16]; uint4 v[2]; } U;
            #pragma unroll
            for (int i = 0; i < 16; i++)
                U.h[i] = __float2half(stg[(rs * 16 + i) * 132 + col]);
            const size_t off = ((size_t)bidx * 1024 + colE) * 2048 + s0 + rs * 16;
            *(uint4*)(o3 + off)     = U.v[0];
            *(uint4*)(o3 + off + 8) = U.v[1];
        }
    }
}

// ---------------------------------------------------------------------------
// Input conversion: X -> fp16 single, W_qkv -> fp16 hi/lo, W_out -> fp16 single
// ---------------------------------------------------------------------------
__global__ void conv_all(const float4* __restrict__ X,  __half* __restrict__ Xf, int n1,
                         const float4* __restrict__ Wq, __half* __restrict__ Wqh,
                         __half* __restrict__ Wql, int n2,
                         const float4* __restrict__ Wo, __half* __restrict__ Wof, int n3)
{
    int i = blockIdx.x * 256 + threadIdx.x;
    if (i < n1) {
        const float4 v = X[i];
        union { __half h[4]; uint2 u; } U;
        U.h[0] = __float2half(v.x); U.h[1] = __float2half(v.y);
        U.h[2] = __float2half(v.z); U.h[3] = __float2half(v.w);
        *(uint2*)(Xf + (size_t)i * 4) = U.u;
    } else if (i < n1 + n2) {
        i -= n1;
        const float4 v = Wq[i];
        const float vv[4] = {v.x, v.y, v.z, v.w};
        union { __half h[4]; uint2 u; } H, L;
        #pragma unroll
        for (int k = 0; k < 4; k++) {
            __half hi = __float2half(vv[k]);
            H.h[k] = hi;
            L.h[k] = __float2half(vv[k] - __half2float(hi));
        }
        *(uint2*)(Wqh + (size_t)i * 4) = H.u;
        *(uint2*)(Wql + (size_t)i * 4) = L.u;
    } else if (i < n1 + n2 + n3) {
        i -= n1 + n2;
        const float4 v = Wo[i];
        union { __half h[4]; uint2 u; } U;
        U.h[0] = __float2half(v.x); U.h[1] = __float2half(v.y);
        U.h[2] = __float2half(v.z); U.h[3] = __float2half(v.w);
        *(uint2*)(Wof + (size_t)i * 4) = U.u;
    }
}

// ---------------------------------------------------------------------------
// Masked softmax; emits att single fp16. Vectorized.
// ---------------------------------------------------------------------------
__global__ void __launch_bounds__(256)
softmax_k(const float* __restrict__ att, const int* __restrict__ mask,
          __half* __restrict__ oh)
{
    const size_t row = blockIdx.x;
    const float4* a4 = (const float4*)(att  + row * (size_t)SLEN);
    const int4*   m4 = (const int4*)  (mask + row * (size_t)SLEN);
    const int tid = threadIdx.x;

    float v[8];
    const float4 x0 = a4[tid], x1 = a4[tid + 256];
    const int4   q0 = m4[tid], q1 = m4[tid + 256];
    v[0] = q0.x ? x0.x : -INFINITY;
    v[1] = q0.y ? x0.y : -INFINITY;
    v[2] = q0.z ? x0.z : -INFINITY;
    v[3] = q0.w ? x0.w : -INFINITY;
    v[4] = q1.x ? x1.x : -INFINITY;
    v[5] = q1.y ? x1.y : -INFINITY;
    v[6] = q1.z ? x1.z : -INFINITY;
    v[7] = q1.w ? x1.w : -INFINITY;

    float lmax = v[0];
    #pragma unroll
    for (int i = 1; i < 8; i++) lmax = fmaxf(lmax, v[i]);

    __shared__ float smax[8], ssum[8];
    #pragma unroll
    for (int o = 16; o > 0; o >>= 1)
        lmax = fmaxf(lmax, __shfl_xor_sync(0xffffffffu, lmax, o));
    if ((tid & 31) == 0) smax[tid >> 5] = lmax;
    __syncthreads();
    const float gmax = fmaxf(fmaxf(fmaxf(smax[0], smax[1]), fmaxf(smax[2], smax[3])),
                             fmaxf(fmaxf(smax[4], smax[5]), fmaxf(smax[6], smax[7])));
    float lsum = 0.0f;
    #pragma unroll
    for (int i = 0; i < 8; i++) { v[i] = __expf(v[i] - gmax); lsum += v[i]; }
    #pragma unroll
    for (int o = 16; o > 0; o >>= 1)
        lsum += __shfl_xor_sync(0xffffffffu, lsum, o);
    if ((tid & 31) == 0) ssum[tid >> 5] = lsum;
    __syncthreads();
    const float gsum = (ssum[0] + ssum[1]) + (ssum[2] + ssum[3])
                     + (ssum[4] + ssum[5]) + (ssum[6] + ssum[7]);
    const float inv = 1.0f / gsum;

    union { __half h[4]; uint2 u; } H0, H1;
    #pragma unroll
    for (int i = 0; i < 4; i++) H0.h[i] = __float2half(v[i] * inv);
    #pragma unroll
    for (int i = 0; i < 4; i++) H1.h[i] = __float2half(v[4 + i] * inv);
    const size_t base = row * (size_t)SLEN;
    *(uint2*)(oh + base + tid * 4)        = H0.u;
    *(uint2*)(oh + base + 1024 + tid * 4) = H1.u;
}

// ---------------------------------------------------------------------------
extern "C" void kernel_launch(void* const* d_in, const int* in_sizes, int n_in,
                              void* d_out, int out_size)
{
    const float* X     = (const float*)d_in[0];
    const int*   mask  = (const int*)  d_in[1];
    const float* W_qkv = (const float*)d_in[2];
    const float* b_qkv = (const float*)d_in[3];
    const float* W_out = (const float*)d_in[4];
    const float* b_out = (const float*)d_in[5];
    float*       out   = (float*)d_out;

    __half *Xf, *Wqh, *Wql, *Wof, *qf, *kf, *vtf, *athf, *cfh, *cfl;
    float *att;
    cudaGetSymbolAddress((void**)&Xf,   g_Xf);
    cudaGetSymbolAddress((void**)&Wqh,  g_Wqh);  cudaGetSymbolAddress((void**)&Wql,  g_Wql);
    cudaGetSymbolAddress((void**)&Wof,  g_Wof);
    cudaGetSymbolAddress((void**)&qf,   g_qf);
    cudaGetSymbolAddress((void**)&kf,   g_kf);
    cudaGetSymbolAddress((void**)&vtf,  g_vtf);
    cudaGetSymbolAddress((void**)&att,  g_att);
    cudaGetSymbolAddress((void**)&athf, g_athf);
    cudaGetSymbolAddress((void**)&cfh,  g_cfh);  cudaGetSymbolAddress((void**)&cfl,  g_cfl);

    cudaFuncSetAttribute(hgemm_k<0>, cudaFuncAttributeMaxDynamicSharedMemorySize, HG_SMEM3);
    cudaFuncSetAttribute(hgemm_k<1>, cudaFuncAttributeMaxDynamicSharedMemorySize, HG_SMEM2);
    cudaFuncSetAttribute(hgemm_k<2>, cudaFuncAttributeMaxDynamicSharedMemorySize, HG_SMEM2);
    cudaFuncSetAttribute(hgemm_k<3>, cudaFuncAttributeMaxDynamicSharedMemorySize, HG_SMEM3);

    // Convert inputs (single launch)
    {
        const int n1 = BATCH*SLEN*EMB/4, n2 = QKVF*EMB/4, n3 = EMB*EMB/4;
        conv_all<<<(n1 + n2 + n3 + 255)/256, 256>>>(
            (const float4*)X, Xf, n1,
            (const float4*)W_qkv, Wqh, Wql, n2,
            (const float4*)W_out, Wof, n3);
    }

    // 1) qkv = X @ W_qkv^T + b — X single, Wq split -> q fp16, k fp16, V^T fp16
    hgemm_k<0><<<dim3(QKVF/128, (BATCH*SLEN)/128), 256, HG_SMEM3>>>(
        Wqh, Wql, Xf,
        0, EMB, 0, EMB, EMB, 1.0f,
        nullptr, 0, 0, qf, kf, vtf, b_qkv);

    // 2) att = (Q @ K^T) / 32 — pure fp16 (fp32 out, per batch)
    hgemm_k<1><<<dim3(SLEN/128, SLEN/128, BATCH), 256, HG_SMEM2>>>(
        kf, nullptr, qf,
        (size_t)SLEN*EMB, EMB, (size_t)SLEN*EMB, EMB, EMB, 0.03125f,
        att, (size_t)SLEN*SLEN, SLEN, nullptr, nullptr, nullptr, nullptr);

    // 3) masked softmax -> att single fp16
    softmax_k<<<BATCH*SLEN, 256>>>(att, mask, athf);

    // 4) ctx = att @ V — pure fp16 -> ctx fp16 hi/lo
    hgemm_k<2><<<dim3(EMB/128, SLEN/128, BATCH), 256, HG_SMEM2>>>(
        vtf, nullptr, athf,
        (size_t)EMB*SLEN, SLEN, (size_t)SLEN*SLEN, SLEN, SLEN, 1.0f,
        nullptr, 0, 0, cfh, cfl, nullptr, nullptr);

    // 5) out = ctx @ W_out^T + b — ctx split, W_out single (fp32 out)
    hgemm_k<3><<<dim3(EMB/128, (BATCH*SLEN)/128), 256, HG_SMEM3>>>(
        cfh, cfl, Wof,
        0, EMB, 0, EMB, EMB, 1.0f,
        out, 0, EMB, nullptr, nullptr, nullptr, b_out);
}